// round 2
// baseline (speedup 1.0000x reference)
#include <cuda_runtime.h>

#define D_IN   128
#define D_H    256
#define KCL    16
#define TM     64
#define NTHREADS 256

// SMEM layout (floats):
//   W1s   [128][256]                         32768
//   HB    union: xs[64][128] / hs[64][260]   16640
//   W2T   [16][260]                           4160
//   b1s   [256], b2s [16]
#define SM_W1   0
#define SM_HB   (32768)
#define SM_W2T  (32768 + 16640)
#define SM_B1   (32768 + 16640 + 4160)
#define SM_B2   (32768 + 16640 + 4160 + 256)
#define SM_FLOATS (32768 + 16640 + 4160 + 256 + 16)
#define SMEM_BYTES (SM_FLOATS * 4)

#define HS_PITCH 260
#define W2T_PITCH 260

__device__ float g_edge_sum;
__device__ int   g_idx_is64;

__global__ __launch_bounds__(NTHREADS, 1)
void fused_mlp_softmax(const float* __restrict__ x,
                       const float* __restrict__ W1,
                       const float* __restrict__ b1,
                       const float* __restrict__ W2,
                       const float* __restrict__ b2,
                       float* __restrict__ C,
                       int N)
{
    extern __shared__ float smem[];
    float* W1s = smem + SM_W1;
    float* HB  = smem + SM_HB;
    float* W2T = smem + SM_W2T;
    float* b1s = smem + SM_B1;
    float* b2s = smem + SM_B2;

    const int tid = threadIdx.x;

    // ---- load weights into SMEM ----
    {
        const float4* W1v = (const float4*)W1;
        float4* W1sv = (float4*)W1s;
        #pragma unroll 4
        for (int i = tid; i < (D_IN * D_H) / 4; i += NTHREADS)
            W1sv[i] = W1v[i];
    }
    for (int i = tid; i < D_H * KCL; i += NTHREADS) {
        int j  = i / KCL;
        int kk = i % KCL;
        W2T[kk * W2T_PITCH + j] = W2[i];
    }
    if (tid < D_H) b1s[tid] = b1[tid];
    if (tid < KCL) b2s[tid] = b2[tid];

    // ---- load x tile [TM][128] (coalesced float4) ----
    const int row_base = blockIdx.x * TM;
    float* xs = HB;  // [64][128]
    {
        float4* xsv = (float4*)xs;
        const float4* xv = (const float4*)x;
        #pragma unroll
        for (int i = tid; i < TM * (D_IN / 4); i += NTHREADS) {
            int r  = i / (D_IN / 4);
            int c4 = i % (D_IN / 4);
            int gr = row_base + r;
            float4 v = make_float4(0.f, 0.f, 0.f, 0.f);
            if (gr < N) v = xv[(size_t)gr * (D_IN / 4) + c4];
            xsv[r * (D_IN / 4) + c4] = v;
        }
    }
    __syncthreads();

    // ---- layer 1: h = relu(x @ W1 + b1); 64x256 tile; 8x8 per thread ----
    const int tx = tid & 31;
    const int ty = tid >> 5;
    const int j0 = tx * 8;
    const int r0 = ty * 8;

    float acc[8][8];
    #pragma unroll
    for (int i = 0; i < 8; i++)
        #pragma unroll
        for (int j = 0; j < 8; j++) acc[i][j] = 0.f;

    #pragma unroll 4
    for (int k = 0; k < D_IN; k++) {
        float a[8];
        #pragma unroll
        for (int i = 0; i < 8; i++)
            a[i] = xs[(r0 + i) * D_IN + k];          // warp-broadcast
        float4 blo = *(const float4*)&W1s[k * D_H + j0];
        float4 bhi = *(const float4*)&W1s[k * D_H + j0 + 4];
        float bb[8] = {blo.x, blo.y, blo.z, blo.w, bhi.x, bhi.y, bhi.z, bhi.w};
        #pragma unroll
        for (int i = 0; i < 8; i++)
            #pragma unroll
            for (int j = 0; j < 8; j++)
                acc[i][j] = fmaf(a[i], bb[j], acc[i][j]);
    }
    __syncthreads();  // done with xs; HB becomes hs

    float* hs = HB;  // [64][HS_PITCH]
    #pragma unroll
    for (int i = 0; i < 8; i++) {
        #pragma unroll
        for (int j = 0; j < 8; j++) {
            float v = acc[i][j] + b1s[j0 + j];
            acc[i][j] = v > 0.f ? v : 0.f;
        }
        *(float4*)&hs[(r0 + i) * HS_PITCH + j0] =
            make_float4(acc[i][0], acc[i][1], acc[i][2], acc[i][3]);
        *(float4*)&hs[(r0 + i) * HS_PITCH + j0 + 4] =
            make_float4(acc[i][4], acc[i][5], acc[i][6], acc[i][7]);
    }
    __syncthreads();

    // ---- layer 2: S = h @ W2 + b2; thread = (4 rows, 1 col) ----
    const int kk  = tid & 15;
    const int rg  = tid >> 4;
    const int rr0 = rg * 4;

    float s0 = 0.f, s1 = 0.f, s2 = 0.f, s3 = 0.f;
    #pragma unroll 8
    for (int j = 0; j < D_H; j += 4) {
        float4 w  = *(const float4*)&W2T[kk * W2T_PITCH + j];
        float4 h0 = *(const float4*)&hs[(rr0 + 0) * HS_PITCH + j];
        float4 h1 = *(const float4*)&hs[(rr0 + 1) * HS_PITCH + j];
        float4 h2 = *(const float4*)&hs[(rr0 + 2) * HS_PITCH + j];
        float4 h3 = *(const float4*)&hs[(rr0 + 3) * HS_PITCH + j];
        s0 = fmaf(h0.x, w.x, fmaf(h0.y, w.y, fmaf(h0.z, w.z, fmaf(h0.w, w.w, s0))));
        s1 = fmaf(h1.x, w.x, fmaf(h1.y, w.y, fmaf(h1.z, w.z, fmaf(h1.w, w.w, s1))));
        s2 = fmaf(h2.x, w.x, fmaf(h2.y, w.y, fmaf(h2.z, w.z, fmaf(h2.w, w.w, s2))));
        s3 = fmaf(h3.x, w.x, fmaf(h3.y, w.y, fmaf(h3.z, w.z, fmaf(h3.w, w.w, s3))));
    }
    float sv[4];
    sv[0] = s0 + b2s[kk];
    sv[1] = s1 + b2s[kk];
    sv[2] = s2 + b2s[kk];
    sv[3] = s3 + b2s[kk];

    // ---- softmax across 16-lane segments (one row per segment) ----
    #pragma unroll
    for (int i = 0; i < 4; i++) {
        float v = sv[i];
        float m = v;
        #pragma unroll
        for (int off = 8; off > 0; off >>= 1)
            m = fmaxf(m, __shfl_xor_sync(0xFFFFFFFFu, m, off, 16));
        float e = __expf(v - m);
        float ssum = e;
        #pragma unroll
        for (int off = 8; off > 0; off >>= 1)
            ssum += __shfl_xor_sync(0xFFFFFFFFu, ssum, off, 16);
        sv[i] = e / ssum;
    }

    #pragma unroll
    for (int i = 0; i < 4; i++) {
        int gr = row_base + rr0 + i;
        if (gr < N) C[(size_t)gr * KCL + kk] = sv[i];
    }
}

// Probe edge_index dtype: under int64 (little-endian), every odd 32-bit word is
// the zero high-half of an index < 2^31. Under int32 those words are live random
// indices. Sampled words 2j+1 (j < E) are in-bounds for BOTH interpretations.
// Also zeroes the edge-sum accumulator (every launch -> graph-replay safe).
__global__ void probe_and_zero_kernel(const int* __restrict__ ei32, int E)
{
    const int tid = threadIdx.x;          // 256 threads, 8 samples each
    int any = 0;
    #pragma unroll
    for (int s = 0; s < 8; s++) {
        int sample = tid * 8 + s;         // 0..2047
        long long j = ((long long)sample * E) >> 11;   // spread over [0, E)
        any |= ei32[2 * j + 1];
    }
    any = __syncthreads_or(any);
    if (tid == 0) {
        g_idx_is64 = (any == 0);
        g_edge_sum = 0.f;
    }
}

__inline__ __device__ float warp_reduce_sum(float v) {
    #pragma unroll
    for (int o = 16; o > 0; o >>= 1)
        v += __shfl_xor_sync(0xFFFFFFFFu, v, o);
    return v;
}

__device__ __forceinline__ float edge_dot(const float* __restrict__ C,
                                          int u, int v, int N) {
    u = ((unsigned)u < (unsigned)N) ? u : 0;   // defensive: never OOB
    v = ((unsigned)v < (unsigned)N) ? v : 0;
    const float4* cu = (const float4*)(C + (size_t)u * KCL);
    const float4* cv = (const float4*)(C + (size_t)v * KCL);
    float4 a0 = __ldg(&cu[0]), a1 = __ldg(&cu[1]), a2 = __ldg(&cu[2]), a3 = __ldg(&cu[3]);
    float4 b0 = __ldg(&cv[0]), b1 = __ldg(&cv[1]), b2 = __ldg(&cv[2]), b3 = __ldg(&cv[3]);
    return a0.x*b0.x + a0.y*b0.y + a0.z*b0.z + a0.w*b0.w
         + a1.x*b1.x + a1.y*b1.y + a1.z*b1.z + a1.w*b1.w
         + a2.x*b2.x + a2.y*b2.y + a2.z*b2.z + a2.w*b2.w
         + a3.x*b3.x + a3.y*b3.y + a3.z*b3.z + a3.w*b3.w;
}

__global__ __launch_bounds__(256)
void edge_sum_kernel(const void* __restrict__ ei_raw,
                     const float* __restrict__ C,
                     int E, int N)
{
    const int is64 = g_idx_is64;          // uniform
    int i = blockIdx.x * blockDim.x + threadIdx.x;
    const int stride = gridDim.x * blockDim.x;
    float part = 0.f;
    if (is64) {
        const long long* ei = (const long long*)ei_raw;
        for (; i < E; i += stride)
            part += edge_dot(C, (int)ei[i], (int)ei[(size_t)E + i], N);
    } else {
        const int* ei = (const int*)ei_raw;
        for (; i < E; i += stride)
            part += edge_dot(C, ei[i], ei[(size_t)E + i], N);
    }
    part = warp_reduce_sum(part);
    __shared__ float ws[8];
    int lane = threadIdx.x & 31, wid = threadIdx.x >> 5;
    if (lane == 0) ws[wid] = part;
    __syncthreads();
    if (wid == 0) {
        float v = (lane < 8) ? ws[lane] : 0.f;
        v = warp_reduce_sum(v);
        if (lane == 0) atomicAdd(&g_edge_sum, v);
    }
}

__global__ void finalize_kernel(float* __restrict__ out, int E, int nk_off, int do_write)
{
    if (do_write)
        out[nk_off] = -g_edge_sum / (float)E;
}

extern "C" void kernel_launch(void* const* d_in, const int* in_sizes, int n_in,
                              void* d_out, int out_size)
{
    const float* x  = (const float*)d_in[0];
    const void*  ei = d_in[1];
    const float* W1 = (const float*)d_in[2];
    const float* b1 = (const float*)d_in[3];
    const float* W2 = (const float*)d_in[4];
    const float* b2 = (const float*)d_in[5];
    float* out = (float*)d_out;

    const int N = in_sizes[0] / D_IN;
    const int E = in_sizes[1] / 2;

    cudaFuncSetAttribute(fused_mlp_softmax,
                         cudaFuncAttributeMaxDynamicSharedMemorySize, SMEM_BYTES);

    const int ntiles = (N + TM - 1) / TM;
    fused_mlp_softmax<<<ntiles, NTHREADS, SMEM_BYTES>>>(x, W1, b1, W2, b2, out, N);

    probe_and_zero_kernel<<<1, 256>>>((const int*)ei, E);

    edge_sum_kernel<<<1184, 256>>>(ei, out, E, N);

    const int nk = N * KCL;
    finalize_kernel<<<1, 1>>>(out, E, nk, out_size > nk ? 1 : 0);
}

// round 3
// speedup vs baseline: 2.2193x; 2.2193x over previous
#include <cuda_runtime.h>
#include <cstdint>

#define D_IN 128
#define D_H  256
#define KCL  16
#define TM   128
#define NT   512

#define XP 132      // xs pitch  (== 4 mod 32 -> conflict-free A-frag loads)
#define WP 264      // W1s pitch (== 8 mod 32 -> conflict-free B-frag loads)
#define HP 260      // hs pitch
#define W2P 260     // W2T pitch

// float offsets in dynamic smem
#define SM_XS  0
#define SM_W1  (TM * XP)                    // 16896
#define SM_W2T (TM * XP + D_IN * WP)        // 50688
#define SM_B1  (SM_W2T + KCL * W2P)         // 54848
#define SM_B2  (SM_B1 + D_H)                // 55104
#define SM_TOT (SM_B2 + KCL)                // 55120 floats
#define SMEM_BYTES (SM_TOT * 4)             // 220480 B

__device__ float g_edge_sum;
__device__ int   g_idx_is64;

__device__ __forceinline__ uint32_t f2tf32(float f) {
    uint32_t r;
    asm("cvt.rna.tf32.f32 %0, %1;" : "=r"(r) : "f"(f));
    return r;
}

__device__ __forceinline__ void mma_tf32(float* d, const uint32_t* a, const uint32_t* b) {
    asm volatile(
        "mma.sync.aligned.m16n8k8.row.col.f32.tf32.tf32.f32 "
        "{%0,%1,%2,%3}, {%4,%5,%6,%7}, {%8,%9}, {%0,%1,%2,%3};"
        : "+f"(d[0]), "+f"(d[1]), "+f"(d[2]), "+f"(d[3])
        : "r"(a[0]), "r"(a[1]), "r"(a[2]), "r"(a[3]), "r"(b[0]), "r"(b[1]));
}

__global__ __launch_bounds__(NT, 1)
void fused_mlp_softmax(const float* __restrict__ x,
                       const float* __restrict__ W1,
                       const float* __restrict__ b1,
                       const float* __restrict__ W2,
                       const float* __restrict__ b2,
                       float* __restrict__ C,
                       int N)
{
    extern __shared__ float sm[];
    float* xs  = sm + SM_XS;   // [128][132]
    float* W1s = sm + SM_W1;   // [128][264]  (k-major)
    float* W2T = sm + SM_W2T;  // [16][260]
    float* b1s = sm + SM_B1;
    float* b2s = sm + SM_B2;

    const int tid = threadIdx.x;
    const int row_base = blockIdx.x * TM;

    // ---- W1 -> smem [k][n], pitch 264, float4 stores ----
    {
        const float4* W1v = (const float4*)W1;
        #pragma unroll 4
        for (int i = tid; i < D_IN * (D_H / 4); i += NT) {
            int k = i >> 6, n4 = i & 63;
            float4 w = W1v[i];
            *(float4*)&W1s[k * WP + 4 * n4] = w;
        }
    }
    // ---- W2 transposed [kk][j] ----
    for (int i = tid; i < D_H * KCL; i += NT) {
        int j = i / KCL, kk = i % KCL;
        W2T[kk * W2P + j] = W2[i];
    }
    if (tid < D_H) b1s[tid] = b1[tid];
    if (tid < KCL) b2s[tid] = b2[tid];

    // ---- x tile -> smem [128][132] ----
    {
        const float4* xv = (const float4*)x;
        #pragma unroll
        for (int i = tid; i < TM * (D_IN / 4); i += NT) {
            int r = i >> 5, c4 = i & 31;
            int gr = row_base + r;
            float4 v = make_float4(0.f, 0.f, 0.f, 0.f);
            if (gr < N) v = xv[(size_t)gr * (D_IN / 4) + c4];
            *(float4*)&xs[r * XP + 4 * c4] = v;
        }
    }
    __syncthreads();

    // ---- layer 1: tf32 mma.sync, block 128x256, warp 32x64 ----
    const int wid  = tid >> 5, lane = tid & 31;
    const int g    = lane >> 2, tg = lane & 3;
    const int rw   = wid >> 2, cw = wid & 3;
    const int rb   = rw * 32;   // warp row base
    const int nb   = cw * 64;   // warp col base

    float acc[2][8][4];
    #pragma unroll
    for (int mf = 0; mf < 2; mf++)
        #pragma unroll
        for (int nf = 0; nf < 8; nf++)
            #pragma unroll
            for (int q = 0; q < 4; q++) acc[mf][nf][q] = 0.f;

    #pragma unroll 1
    for (int k0 = 0; k0 < D_IN; k0 += 8) {
        uint32_t af[2][4];
        #pragma unroll
        for (int mf = 0; mf < 2; mf++) {
            int r0 = rb + mf * 16 + g;
            af[mf][0] = f2tf32(xs[r0 * XP + k0 + tg]);
            af[mf][1] = f2tf32(xs[(r0 + 8) * XP + k0 + tg]);
            af[mf][2] = f2tf32(xs[r0 * XP + k0 + tg + 4]);
            af[mf][3] = f2tf32(xs[(r0 + 8) * XP + k0 + tg + 4]);
        }
        uint32_t bf[8][2];
        #pragma unroll
        for (int nf = 0; nf < 8; nf++) {
            int n = nb + nf * 8 + g;
            bf[nf][0] = f2tf32(W1s[(k0 + tg) * WP + n]);
            bf[nf][1] = f2tf32(W1s[(k0 + tg + 4) * WP + n]);
        }
        #pragma unroll
        for (int mf = 0; mf < 2; mf++)
            #pragma unroll
            for (int nf = 0; nf < 8; nf++)
                mma_tf32(acc[mf][nf], af[mf], bf[nf]);
    }
    __syncthreads();   // all warps done with xs/W1s before overlay

    // ---- bias + relu, write h to smem (overlays xs/W1s) ----
    float* hs = sm;    // [128][260]
    #pragma unroll
    for (int mf = 0; mf < 2; mf++) {
        #pragma unroll
        for (int nf = 0; nf < 8; nf++) {
            int row = rb + mf * 16 + g;
            int col = nb + nf * 8 + 2 * tg;
            float bc0 = b1s[col], bc1 = b1s[col + 1];
            hs[row * HP + col]           = fmaxf(acc[mf][nf][0] + bc0, 0.f);
            hs[row * HP + col + 1]       = fmaxf(acc[mf][nf][1] + bc1, 0.f);
            hs[(row + 8) * HP + col]     = fmaxf(acc[mf][nf][2] + bc0, 0.f);
            hs[(row + 8) * HP + col + 1] = fmaxf(acc[mf][nf][3] + bc1, 0.f);
        }
    }
    __syncthreads();

    // ---- layer 2: S = h @ W2 + b2 (fp32); thread = (4 rows, 1 col) ----
    const int kk  = tid & 15;
    const int rg  = tid >> 4;     // 0..31
    const int rr0 = rg * 4;

    float s0 = 0.f, s1 = 0.f, s2 = 0.f, s3 = 0.f;
    #pragma unroll 8
    for (int j = 0; j < D_H; j += 4) {
        float4 w  = *(const float4*)&W2T[kk * W2P + j];
        float4 h0 = *(const float4*)&hs[(rr0 + 0) * HP + j];
        float4 h1 = *(const float4*)&hs[(rr0 + 1) * HP + j];
        float4 h2 = *(const float4*)&hs[(rr0 + 2) * HP + j];
        float4 h3 = *(const float4*)&hs[(rr0 + 3) * HP + j];
        s0 = fmaf(h0.x, w.x, fmaf(h0.y, w.y, fmaf(h0.z, w.z, fmaf(h0.w, w.w, s0))));
        s1 = fmaf(h1.x, w.x, fmaf(h1.y, w.y, fmaf(h1.z, w.z, fmaf(h1.w, w.w, s1))));
        s2 = fmaf(h2.x, w.x, fmaf(h2.y, w.y, fmaf(h2.z, w.z, fmaf(h2.w, w.w, s2))));
        s3 = fmaf(h3.x, w.x, fmaf(h3.y, w.y, fmaf(h3.z, w.z, fmaf(h3.w, w.w, s3))));
    }
    float sv[4];
    sv[0] = s0 + b2s[kk];
    sv[1] = s1 + b2s[kk];
    sv[2] = s2 + b2s[kk];
    sv[3] = s3 + b2s[kk];

    // ---- softmax across 16-lane segments ----
    #pragma unroll
    for (int i = 0; i < 4; i++) {
        float v = sv[i];
        float m = v;
        #pragma unroll
        for (int off = 8; off > 0; off >>= 1)
            m = fmaxf(m, __shfl_xor_sync(0xFFFFFFFFu, m, off, 16));
        float e = __expf(v - m);
        float ssum = e;
        #pragma unroll
        for (int off = 8; off > 0; off >>= 1)
            ssum += __shfl_xor_sync(0xFFFFFFFFu, ssum, off, 16);
        sv[i] = e / ssum;
    }

    #pragma unroll
    for (int i = 0; i < 4; i++) {
        int gr = row_base + rr0 + i;
        if (gr < N) C[(size_t)gr * KCL + kk] = sv[i];
    }
}

// dtype probe (int64 high words are all zero) + accumulator zeroing
__global__ void probe_and_zero_kernel(const int* __restrict__ ei32, int E)
{
    const int tid = threadIdx.x;
    int any = 0;
    #pragma unroll
    for (int s = 0; s < 8; s++) {
        int sample = tid * 8 + s;
        long long j = ((long long)sample * E) >> 11;
        any |= ei32[2 * j + 1];
    }
    any = __syncthreads_or(any);
    if (tid == 0) {
        g_idx_is64 = (any == 0);
        g_edge_sum = 0.f;
    }
}

__inline__ __device__ float warp_reduce_sum(float v) {
    #pragma unroll
    for (int o = 16; o > 0; o >>= 1)
        v += __shfl_xor_sync(0xFFFFFFFFu, v, o);
    return v;
}

// 4 lanes cooperate per edge: each loads one float4 of C[u] and C[v]
__global__ __launch_bounds__(256)
void edge_sum_kernel(const void* __restrict__ ei_raw,
                     const float* __restrict__ C,
                     int E, int N)
{
    const int is64 = g_idx_is64;          // uniform
    const int tid_g  = blockIdx.x * blockDim.x + threadIdx.x;
    const int lane4  = tid_g & 3;
    int q = tid_g >> 2;
    const int nquads = (gridDim.x * blockDim.x) >> 2;
    const float4* C4 = (const float4*)C;

    float part = 0.f;
    if (is64) {
        const long long* ei = (const long long*)ei_raw;
        for (int e = q; e < E; e += nquads) {
            int u = (int)ei[e];
            int v = (int)ei[(size_t)E + e];
            u = ((unsigned)u < (unsigned)N) ? u : 0;
            v = ((unsigned)v < (unsigned)N) ? v : 0;
            float4 a = __ldg(&C4[(size_t)u * 4 + lane4]);
            float4 b = __ldg(&C4[(size_t)v * 4 + lane4]);
            part += a.x * b.x + a.y * b.y + a.z * b.z + a.w * b.w;
        }
    } else {
        const int* ei = (const int*)ei_raw;
        for (int e = q; e < E; e += nquads) {
            int u = ei[e];
            int v = ei[(size_t)E + e];
            u = ((unsigned)u < (unsigned)N) ? u : 0;
            v = ((unsigned)v < (unsigned)N) ? v : 0;
            float4 a = __ldg(&C4[(size_t)u * 4 + lane4]);
            float4 b = __ldg(&C4[(size_t)v * 4 + lane4]);
            part += a.x * b.x + a.y * b.y + a.z * b.z + a.w * b.w;
        }
    }

    part = warp_reduce_sum(part);
    __shared__ float ws[8];
    int lane = threadIdx.x & 31, wrp = threadIdx.x >> 5;
    if (lane == 0) ws[wrp] = part;
    __syncthreads();
    if (wrp == 0) {
        float v = (lane < 8) ? ws[lane] : 0.f;
        v = warp_reduce_sum(v);
        if (lane == 0) atomicAdd(&g_edge_sum, v);
    }
}

__global__ void finalize_kernel(float* __restrict__ out, int E, int nk_off, int do_write)
{
    if (do_write)
        out[nk_off] = -g_edge_sum / (float)E;
}

extern "C" void kernel_launch(void* const* d_in, const int* in_sizes, int n_in,
                              void* d_out, int out_size)
{
    const float* x  = (const float*)d_in[0];
    const void*  ei = d_in[1];
    const float* W1 = (const float*)d_in[2];
    const float* b1 = (const float*)d_in[3];
    const float* W2 = (const float*)d_in[4];
    const float* b2 = (const float*)d_in[5];
    float* out = (float*)d_out;

    const int N = in_sizes[0] / D_IN;
    const int E = in_sizes[1] / 2;

    cudaFuncSetAttribute(fused_mlp_softmax,
                         cudaFuncAttributeMaxDynamicSharedMemorySize, SMEM_BYTES);

    const int ntiles = (N + TM - 1) / TM;
    fused_mlp_softmax<<<ntiles, NT, SMEM_BYTES>>>(x, W1, b1, W2, b2, out, N);

    probe_and_zero_kernel<<<1, 256>>>((const int*)ei, E);

    edge_sum_kernel<<<1184, 256>>>(ei, out, E, N);

    const int nk = N * KCL;
    finalize_kernel<<<1, 1>>>(out, E, nk, out_size > nk ? 1 : 0);
}

// round 4
// speedup vs baseline: 2.6632x; 1.2000x over previous
#include <cuda_runtime.h>
#include <cuda_bf16.h>
#include <cstdint>

#define D_IN 128
#define D_H  256
#define KCL  16
#define TM   128
#define NT   512

#define XP 132      // xs pitch  (== 4 mod 32)
#define WP 264      // W1s pitch (== 8 mod 32)
#define W2P 260     // W2T pitch
#define PP  66      // P partial pitch

// float offsets in dynamic smem (phase 0/1 view)
#define SM_XS  0
#define SM_W1  (TM * XP)                    // 16896
#define SM_W2T (SM_W1 + D_IN * WP)          // 50688
#define SM_B1  (SM_W2T + KCL * W2P)         // 54848
#define SM_B2  (SM_B1 + D_H)                // 55104
#define SM_TOT (SM_B2 + KCL)                // 55120 floats
#define SMEM_BYTES (SM_TOT * 4)             // 220480 B

// overlay (phase 2+): staging [16 warps][32 rows][64 tf32] then P [128][66]
#define SM_STAGE 0
#define SM_P     32768

#define CB_CAP 131072
__device__ uint4 g_Cb[CB_CAP * 2];          // bf16 copy of C, 32B/row
__device__ float g_edge_sum;
__device__ int   g_idx_is64;

__device__ __forceinline__ uint32_t f2tf32(float f) {
    uint32_t r;
    asm("cvt.rna.tf32.f32 %0, %1;" : "=r"(r) : "f"(f));
    return r;
}

__device__ __forceinline__ void mma_tf32(float* d, const uint32_t* a, const uint32_t* b) {
    asm volatile(
        "mma.sync.aligned.m16n8k8.row.col.f32.tf32.tf32.f32 "
        "{%0,%1,%2,%3}, {%4,%5,%6,%7}, {%8,%9}, {%0,%1,%2,%3};"
        : "+f"(d[0]), "+f"(d[1]), "+f"(d[2]), "+f"(d[3])
        : "r"(a[0]), "r"(a[1]), "r"(a[2]), "r"(a[3]), "r"(b[0]), "r"(b[1]));
}

__global__ __launch_bounds__(NT, 1)
void fused_mlp_softmax(const float* __restrict__ x,
                       const float* __restrict__ W1,
                       const float* __restrict__ b1,
                       const float* __restrict__ W2,
                       const float* __restrict__ b2,
                       float* __restrict__ C,
                       int N, int write_bf16)
{
    extern __shared__ float sm[];
    float*    xs   = sm + SM_XS;                 // [128][132]
    float*    W1s  = sm + SM_W1;                 // [128][264] k-major
    uint32_t* W2T  = (uint32_t*)(sm + SM_W2T);   // [16][260] tf32 bits
    float*    b1s  = sm + SM_B1;
    float*    b2s  = sm + SM_B2;

    const int tid = threadIdx.x;
    const int row_base = blockIdx.x * TM;

    // ---- phase 0: weights + x tile ----
    {
        const float4* W1v = (const float4*)W1;
        #pragma unroll 4
        for (int i = tid; i < D_IN * (D_H / 4); i += NT) {
            int k = i >> 6, n4 = i & 63;
            *(float4*)&W1s[k * WP + 4 * n4] = W1v[i];
        }
    }
    for (int i = tid; i < D_H * KCL; i += NT) {
        int j = i / KCL, kk = i % KCL;
        W2T[kk * W2P + j] = f2tf32(W2[i]);       // pre-convert to tf32 bits
    }
    if (tid < D_H) b1s[tid] = b1[tid];
    if (tid < KCL) b2s[tid] = b2[tid];
    {
        const float4* xv = (const float4*)x;
        #pragma unroll
        for (int i = tid; i < TM * (D_IN / 4); i += NT) {
            int r = i >> 5, c4 = i & 31;
            int gr = row_base + r;
            float4 v = make_float4(0.f, 0.f, 0.f, 0.f);
            if (gr < N) v = xv[(size_t)gr * (D_IN / 4) + c4];
            *(float4*)&xs[r * XP + 4 * c4] = v;
        }
    }
    __syncthreads();

    // ---- phase 1: layer 1 tf32 mma, warp tile 32x64 ----
    const int wid = tid >> 5, lane = tid & 31;
    const int g = lane >> 2, tg = lane & 3;
    const int rw = wid >> 2, cw = wid & 3;
    const int rb = rw * 32;
    const int nb = cw * 64;

    float acc[2][8][4];
    #pragma unroll
    for (int mf = 0; mf < 2; mf++)
        #pragma unroll
        for (int nf = 0; nf < 8; nf++)
            #pragma unroll
            for (int q = 0; q < 4; q++) acc[mf][nf][q] = 0.f;

    #pragma unroll 1
    for (int k0 = 0; k0 < D_IN; k0 += 8) {
        uint32_t af[2][4];
        #pragma unroll
        for (int mf = 0; mf < 2; mf++) {
            int r0 = rb + mf * 16 + g;
            af[mf][0] = f2tf32(xs[r0 * XP + k0 + tg]);
            af[mf][1] = f2tf32(xs[(r0 + 8) * XP + k0 + tg]);
            af[mf][2] = f2tf32(xs[r0 * XP + k0 + tg + 4]);
            af[mf][3] = f2tf32(xs[(r0 + 8) * XP + k0 + tg + 4]);
        }
        uint32_t bf[8][2];
        #pragma unroll
        for (int nf = 0; nf < 8; nf++) {
            int n = nb + nf * 8 + g;
            bf[nf][0] = f2tf32(W1s[(k0 + tg) * WP + n]);
            bf[nf][1] = f2tf32(W1s[(k0 + tg + 4) * WP + n]);
        }
        #pragma unroll
        for (int mf = 0; mf < 2; mf++)
            #pragma unroll
            for (int nf = 0; nf < 8; nf++)
                mma_tf32(acc[mf][nf], af[mf], bf[nf]);
    }
    __syncthreads();   // all warps done reading xs/W1s; safe to overlay

    // ---- phase 2: bias+relu -> tf32 bits -> warp-local swizzled staging ----
    // staging[warp]: 32 rows x 32 float2-groups; group j at row r stored at
    // j' = j ^ (4*(r&7))  -> conflict-free stores, <=2-way load conflicts
    uint32_t* stg = (uint32_t*)sm + SM_STAGE + wid * 2048;
    #pragma unroll
    for (int mf = 0; mf < 2; mf++) {
        #pragma unroll
        for (int nf = 0; nf < 8; nf++) {
            int col = nb + nf * 8 + 2 * tg;
            float bc0 = b1s[col], bc1 = b1s[col + 1];
            int jswz = (4 * nf + tg) ^ (4 * g);
            int r0 = mf * 16 + g;
            uint2 lo, hi;
            lo.x = f2tf32(fmaxf(acc[mf][nf][0] + bc0, 0.f));
            lo.y = f2tf32(fmaxf(acc[mf][nf][1] + bc1, 0.f));
            hi.x = f2tf32(fmaxf(acc[mf][nf][2] + bc0, 0.f));
            hi.y = f2tf32(fmaxf(acc[mf][nf][3] + bc1, 0.f));
            *(uint2*)&stg[r0 * 64 + 2 * jswz]       = lo;
            *(uint2*)&stg[(r0 + 8) * 64 + 2 * jswz] = hi;
        }
    }
    __syncwarp();

    // ---- phase 3: layer 2 via tf32 mma: per-warp M=32, N=16, K=64 ----
    float s2[2][2][4];
    #pragma unroll
    for (int mf = 0; mf < 2; mf++)
        #pragma unroll
        for (int nf2 = 0; nf2 < 2; nf2++)
            #pragma unroll
            for (int q = 0; q < 4; q++) s2[mf][nf2][q] = 0.f;

    const int kofs = cw * 64;  // this warp's K-slice of D_H
    #pragma unroll
    for (int ks = 0; ks < 8; ks++) {
        uint32_t bfr[2][2];
        #pragma unroll
        for (int nf2 = 0; nf2 < 2; nf2++) {
            int n = nf2 * 8 + g;
            bfr[nf2][0] = W2T[n * W2P + kofs + ks * 8 + tg];
            bfr[nf2][1] = W2T[n * W2P + kofs + ks * 8 + tg + 4];
        }
        #pragma unroll
        for (int mf = 0; mf < 2; mf++) {
            int r0 = mf * 16 + g;
            int jA = (4 * ks + (tg >> 1)) ^ (4 * g);
            int jB = (4 * ks + 2 + (tg >> 1)) ^ (4 * g);
            int sl = tg & 1;
            uint32_t a[4];
            a[0] = stg[r0 * 64 + 2 * jA + sl];
            a[1] = stg[(r0 + 8) * 64 + 2 * jA + sl];
            a[2] = stg[r0 * 64 + 2 * jB + sl];
            a[3] = stg[(r0 + 8) * 64 + 2 * jB + sl];
            #pragma unroll
            for (int nf2 = 0; nf2 < 2; nf2++)
                mma_tf32(s2[mf][nf2], a, bfr[nf2]);
        }
    }

    // ---- phase 4: write K-partials P[row][cw][kk], pitch 66 ----
    float* P = sm + SM_P;
    #pragma unroll
    for (int mf = 0; mf < 2; mf++) {
        #pragma unroll
        for (int nf2 = 0; nf2 < 2; nf2++) {
            int row = rb + mf * 16 + g;
            int kk0 = nf2 * 8 + 2 * tg;
            *(float2*)&P[row * PP + cw * 16 + kk0] =
                make_float2(s2[mf][nf2][0], s2[mf][nf2][1]);
            *(float2*)&P[(row + 8) * PP + cw * 16 + kk0] =
                make_float2(s2[mf][nf2][2], s2[mf][nf2][3]);
        }
    }
    __syncthreads();

    // ---- phase 5: reduce partials, softmax, store ----
    const int kk  = tid & 15;
    const int rg  = tid >> 4;
    const int rr0 = rg * 4;
    const float bias2 = b2s[kk];

    float sv[4];
    #pragma unroll
    for (int i = 0; i < 4; i++) {
        const float* Pr = &P[(rr0 + i) * PP + kk];
        sv[i] = Pr[0] + Pr[16] + Pr[32] + Pr[48] + bias2;
    }
    #pragma unroll
    for (int i = 0; i < 4; i++) {
        float v = sv[i];
        float m = v;
        #pragma unroll
        for (int off = 8; off > 0; off >>= 1)
            m = fmaxf(m, __shfl_xor_sync(0xFFFFFFFFu, m, off, 16));
        float e = __expf(v - m);
        float ssum = e;
        #pragma unroll
        for (int off = 8; off > 0; off >>= 1)
            ssum += __shfl_xor_sync(0xFFFFFFFFu, ssum, off, 16);
        sv[i] = e / ssum;
    }

    __nv_bfloat16* Cb16 = (__nv_bfloat16*)g_Cb;
    #pragma unroll
    for (int i = 0; i < 4; i++) {
        int gr = row_base + rr0 + i;
        if (gr < N) {
            C[(size_t)gr * KCL + kk] = sv[i];
            if (write_bf16)
                Cb16[(size_t)gr * KCL + kk] = __float2bfloat16(sv[i]);
        }
    }
}

// dtype probe (int64 high words all zero) + accumulator zeroing
__global__ void probe_and_zero_kernel(const int* __restrict__ ei32, int E)
{
    const int tid = threadIdx.x;
    int any = 0;
    #pragma unroll
    for (int s = 0; s < 8; s++) {
        int sample = tid * 8 + s;
        long long j = ((long long)sample * E) >> 11;
        any |= ei32[2 * j + 1];
    }
    any = __syncthreads_or(any);
    if (tid == 0) {
        g_idx_is64 = (any == 0);
        g_edge_sum = 0.f;
    }
}

__inline__ __device__ float warp_reduce_sum(float v) {
    #pragma unroll
    for (int o = 16; o > 0; o >>= 1)
        v += __shfl_xor_sync(0xFFFFFFFFu, v, o);
    return v;
}

__device__ __forceinline__ float bf16x8_dot(uint4 a, uint4 b) {
    float2 fa, fb;
    float s = 0.f;
    fa = __bfloat1622float2(*(__nv_bfloat162*)&a.x);
    fb = __bfloat1622float2(*(__nv_bfloat162*)&b.x);
    s += fa.x * fb.x + fa.y * fb.y;
    fa = __bfloat1622float2(*(__nv_bfloat162*)&a.y);
    fb = __bfloat1622float2(*(__nv_bfloat162*)&b.y);
    s += fa.x * fb.x + fa.y * fb.y;
    fa = __bfloat1622float2(*(__nv_bfloat162*)&a.z);
    fb = __bfloat1622float2(*(__nv_bfloat162*)&b.z);
    s += fa.x * fb.x + fa.y * fb.y;
    fa = __bfloat1622float2(*(__nv_bfloat162*)&a.w);
    fb = __bfloat1622float2(*(__nv_bfloat162*)&b.w);
    s += fa.x * fb.x + fa.y * fb.y;
    return s;
}

// bf16 path: 2 lanes per edge, each loads 16B of each row (32B/row total)
__global__ __launch_bounds__(256)
void edge_sum_kernel(const void* __restrict__ ei_raw,
                     const float* __restrict__ C,
                     int E, int N, int use_bf16)
{
    const int is64 = g_idx_is64;
    const int tid_g = blockIdx.x * blockDim.x + threadIdx.x;
    const int total = gridDim.x * blockDim.x;
    float part = 0.f;

    if (use_bf16) {
        const uint4* Cb = (const uint4*)g_Cb;
        const int half = tid_g & 1;
        const int p0 = tid_g >> 1;
        const int np = total >> 1;
        if (is64) {
            const long long* ei = (const long long*)ei_raw;
            for (int e = p0; e < E; e += np) {
                int u = (int)ei[e];
                int v = (int)ei[(size_t)E + e];
                u = ((unsigned)u < (unsigned)N) ? u : 0;
                v = ((unsigned)v < (unsigned)N) ? v : 0;
                uint4 a = __ldg(&Cb[(size_t)u * 2 + half]);
                uint4 b = __ldg(&Cb[(size_t)v * 2 + half]);
                part += bf16x8_dot(a, b);
            }
        } else {
            const int* ei = (const int*)ei_raw;
            for (int e = p0; e < E; e += np) {
                int u = ei[e];
                int v = ei[(size_t)E + e];
                u = ((unsigned)u < (unsigned)N) ? u : 0;
                v = ((unsigned)v < (unsigned)N) ? v : 0;
                uint4 a = __ldg(&Cb[(size_t)u * 2 + half]);
                uint4 b = __ldg(&Cb[(size_t)v * 2 + half]);
                part += bf16x8_dot(a, b);
            }
        }
    } else {
        // fp32 fallback: 4 lanes per edge
        const int lane4 = tid_g & 3;
        const int q0 = tid_g >> 2;
        const int nq = total >> 2;
        const float4* C4 = (const float4*)C;
        if (is64) {
            const long long* ei = (const long long*)ei_raw;
            for (int e = q0; e < E; e += nq) {
                int u = (int)ei[e];
                int v = (int)ei[(size_t)E + e];
                u = ((unsigned)u < (unsigned)N) ? u : 0;
                v = ((unsigned)v < (unsigned)N) ? v : 0;
                float4 a = __ldg(&C4[(size_t)u * 4 + lane4]);
                float4 b = __ldg(&C4[(size_t)v * 4 + lane4]);
                part += a.x * b.x + a.y * b.y + a.z * b.z + a.w * b.w;
            }
        } else {
            const int* ei = (const int*)ei_raw;
            for (int e = q0; e < E; e += nq) {
                int u = ei[e];
                int v = ei[(size_t)E + e];
                u = ((unsigned)u < (unsigned)N) ? u : 0;
                v = ((unsigned)v < (unsigned)N) ? v : 0;
                float4 a = __ldg(&C4[(size_t)u * 4 + lane4]);
                float4 b = __ldg(&C4[(size_t)v * 4 + lane4]);
                part += a.x * b.x + a.y * b.y + a.z * b.z + a.w * b.w;
            }
        }
    }

    part = warp_reduce_sum(part);
    __shared__ float ws[8];
    int lane = threadIdx.x & 31, wrp = threadIdx.x >> 5;
    if (lane == 0) ws[wrp] = part;
    __syncthreads();
    if (wrp == 0) {
        float v = (lane < 8) ? ws[lane] : 0.f;
        v = warp_reduce_sum(v);
        if (lane == 0) atomicAdd(&g_edge_sum, v);
    }
}

__global__ void finalize_kernel(float* __restrict__ out, int E, int nk_off, int do_write)
{
    if (do_write)
        out[nk_off] = -g_edge_sum / (float)E;
}

extern "C" void kernel_launch(void* const* d_in, const int* in_sizes, int n_in,
                              void* d_out, int out_size)
{
    const float* x  = (const float*)d_in[0];
    const void*  ei = d_in[1];
    const float* W1 = (const float*)d_in[2];
    const float* b1 = (const float*)d_in[3];
    const float* W2 = (const float*)d_in[4];
    const float* b2 = (const float*)d_in[5];
    float* out = (float*)d_out;

    const int N = in_sizes[0] / D_IN;
    const int E = in_sizes[1] / 2;
    const int use_bf16 = (N <= CB_CAP) ? 1 : 0;

    cudaFuncSetAttribute(fused_mlp_softmax,
                         cudaFuncAttributeMaxDynamicSharedMemorySize, SMEM_BYTES);

    const int ntiles = (N + TM - 1) / TM;
    fused_mlp_softmax<<<ntiles, NT, SMEM_BYTES>>>(x, W1, b1, W2, b2, out, N, use_bf16);

    probe_and_zero_kernel<<<1, 256>>>((const int*)ei, E);

    edge_sum_kernel<<<1184, 256>>>(ei, out, E, N, use_bf16);

    const int nk = N * KCL;
    finalize_kernel<<<1, 1>>>(out, E, nk, out_size > nk ? 1 : 0);
}

// round 5
// speedup vs baseline: 2.7146x; 1.0193x over previous
#include <cuda_runtime.h>
#include <cuda_bf16.h>
#include <cstdint>

#define D_IN 128
#define D_H  256
#define KCL  16
#define TM   128
#define NT   256

#define XP 132      // xs pitch  (== 4 mod 32 -> conflict-free A loads)
#define WP 264      // W1 pitch  (== 8 mod 32 -> conflict-free B loads)
#define W2P 260
#define PP  66

// phase 0/1 smem view (word offsets)
#define SM_XS  0
#define SM_W1  (TM * XP)                    // 16896
#define SM_W2T (SM_W1 + D_IN * WP)          // 50688
#define SM_B1  (SM_W2T + KCL * W2P)         // 54848
#define SM_B2  (SM_B1 + D_H)                // 55104
#define SM_TOT (SM_B2 + KCL)                // 55120
#define SMEM_BYTES (SM_TOT * 4)             // 220480 B

// phase 2+ overlay: staging 8 warps x 64x64 words (32768), then P [128][66]
#define SM_STAGE 0
#define SM_P     32768                      // ends 41216 < SM_W2T (W2T/b1/b2 stay live)

#define CB_CAP 131072
__device__ uint4 g_Cb[CB_CAP * 2];          // bf16 copy of C, 32 B/row
__device__ float g_edge_sum;
__device__ int   g_done;

__device__ __forceinline__ uint32_t f2tf32(float f) {
    uint32_t r;
    asm("cvt.rna.tf32.f32 %0, %1;" : "=r"(r) : "f"(f));
    return r;
}

__device__ __forceinline__ void mma_tf32(float* d, const uint32_t* a, const uint32_t* b) {
    asm volatile(
        "mma.sync.aligned.m16n8k8.row.col.f32.tf32.tf32.f32 "
        "{%0,%1,%2,%3}, {%4,%5,%6,%7}, {%8,%9}, {%0,%1,%2,%3};"
        : "+f"(d[0]), "+f"(d[1]), "+f"(d[2]), "+f"(d[3])
        : "r"(a[0]), "r"(a[1]), "r"(a[2]), "r"(a[3]), "r"(b[0]), "r"(b[1]));
}

__global__ __launch_bounds__(NT, 1)
void fused_mlp_softmax(const float* __restrict__ x,
                       const float* __restrict__ W1,
                       const float* __restrict__ b1,
                       const float* __restrict__ W2,
                       const float* __restrict__ b2,
                       float* __restrict__ C,
                       int N, int write_bf16)
{
    extern __shared__ float sm[];
    uint32_t* xs  = (uint32_t*)(sm + SM_XS);    // [128][132] tf32 bits
    uint32_t* W1b = (uint32_t*)(sm + SM_W1);    // [128][264] tf32 bits, k-major
    uint32_t* W2T = (uint32_t*)(sm + SM_W2T);   // [16][260]  tf32 bits
    float* b1s = sm + SM_B1;
    float* b2s = sm + SM_B2;

    const int tid = threadIdx.x;
    const int row_base = blockIdx.x * TM;

    // ---- phase 0: load + pre-convert everything ----
    {
        const float4* W1v = (const float4*)W1;
        #pragma unroll 4
        for (int i = tid; i < D_IN * (D_H / 4); i += NT) {
            int k = i >> 6, n4 = i & 63;
            float4 w = W1v[i];
            uint4 u;
            u.x = f2tf32(w.x); u.y = f2tf32(w.y);
            u.z = f2tf32(w.z); u.w = f2tf32(w.w);
            *(uint4*)&W1b[k * WP + 4 * n4] = u;
        }
    }
    for (int i = tid; i < D_H * KCL; i += NT) {
        int j = i / KCL, kk = i % KCL;
        W2T[kk * W2P + j] = f2tf32(W2[i]);
    }
    b1s[tid] = b1[tid];                 // NT == D_H
    if (tid < KCL) b2s[tid] = b2[tid];
    {
        const float4* xv = (const float4*)x;
        #pragma unroll
        for (int i = tid; i < TM * (D_IN / 4); i += NT) {
            int r = i >> 5, c4 = i & 31;
            int gr = row_base + r;
            float4 v = make_float4(0.f, 0.f, 0.f, 0.f);
            if (gr < N) v = xv[(size_t)gr * (D_IN / 4) + c4];
            uint4 u;
            u.x = f2tf32(v.x); u.y = f2tf32(v.y);
            u.z = f2tf32(v.z); u.w = f2tf32(v.w);
            *(uint4*)&xs[r * XP + 4 * c4] = u;
        }
    }
    __syncthreads();

    // ---- phase 1: layer 1 tf32 mma, 8 warps, warp tile 64x64 ----
    const int wid = tid >> 5, lane = tid & 31;
    const int g = lane >> 2, tg = lane & 3;
    const int rw = wid >> 2, cw = wid & 3;
    const int rb = rw * 64;
    const int nb = cw * 64;

    float acc[4][8][4];
    #pragma unroll
    for (int mf = 0; mf < 4; mf++)
        #pragma unroll
        for (int nf = 0; nf < 8; nf++)
            #pragma unroll
            for (int q = 0; q < 4; q++) acc[mf][nf][q] = 0.f;

    #pragma unroll 1
    for (int k0 = 0; k0 < D_IN; k0 += 8) {
        uint32_t af[4][4];
        #pragma unroll
        for (int mf = 0; mf < 4; mf++) {
            int r0 = rb + mf * 16 + g;
            af[mf][0] = xs[r0 * XP + k0 + tg];
            af[mf][1] = xs[(r0 + 8) * XP + k0 + tg];
            af[mf][2] = xs[r0 * XP + k0 + tg + 4];
            af[mf][3] = xs[(r0 + 8) * XP + k0 + tg + 4];
        }
        uint32_t bf[8][2];
        #pragma unroll
        for (int nf = 0; nf < 8; nf++) {
            int n = nb + nf * 8 + g;
            bf[nf][0] = W1b[(k0 + tg) * WP + n];
            bf[nf][1] = W1b[(k0 + tg + 4) * WP + n];
        }
        #pragma unroll
        for (int mf = 0; mf < 4; mf++)
            #pragma unroll
            for (int nf = 0; nf < 8; nf++)
                mma_tf32(acc[mf][nf], af[mf], bf[nf]);
    }
    __syncthreads();   // xs/W1b dead; overlay begins

    // ---- phase 2: bias+relu -> tf32 bits -> warp-local swizzled staging ----
    // staging[warp]: 64 rows x 32 word-pairs; pair j at row r stored at j^(4*(r&7))
    uint32_t* stg = (uint32_t*)sm + SM_STAGE + wid * 4096;
    #pragma unroll
    for (int mf = 0; mf < 4; mf++) {
        #pragma unroll
        for (int nf = 0; nf < 8; nf++) {
            int col = nb + nf * 8 + 2 * tg;
            float bc0 = b1s[col], bc1 = b1s[col + 1];
            int jswz = (4 * nf + tg) ^ (4 * g);
            int r0 = mf * 16 + g;
            uint2 lo, hi;
            lo.x = f2tf32(fmaxf(acc[mf][nf][0] + bc0, 0.f));
            lo.y = f2tf32(fmaxf(acc[mf][nf][1] + bc1, 0.f));
            hi.x = f2tf32(fmaxf(acc[mf][nf][2] + bc0, 0.f));
            hi.y = f2tf32(fmaxf(acc[mf][nf][3] + bc1, 0.f));
            *(uint2*)&stg[r0 * 64 + 2 * jswz]       = lo;
            *(uint2*)&stg[(r0 + 8) * 64 + 2 * jswz] = hi;
        }
    }
    __syncwarp();

    // ---- phase 3: layer 2 tf32 mma: per warp M=64, N=16, K=64 (k-slice cw) ----
    float s2[4][2][4];
    #pragma unroll
    for (int mf = 0; mf < 4; mf++)
        #pragma unroll
        for (int nf2 = 0; nf2 < 2; nf2++)
            #pragma unroll
            for (int q = 0; q < 4; q++) s2[mf][nf2][q] = 0.f;

    const int kofs = cw * 64;
    #pragma unroll
    for (int ks = 0; ks < 8; ks++) {
        uint32_t bfr[2][2];
        #pragma unroll
        for (int nf2 = 0; nf2 < 2; nf2++) {
            int n = nf2 * 8 + g;
            bfr[nf2][0] = W2T[n * W2P + kofs + ks * 8 + tg];
            bfr[nf2][1] = W2T[n * W2P + kofs + ks * 8 + tg + 4];
        }
        #pragma unroll
        for (int mf = 0; mf < 4; mf++) {
            int r0 = mf * 16 + g;
            int jA = (4 * ks + (tg >> 1)) ^ (4 * g);
            int jB = (4 * ks + 2 + (tg >> 1)) ^ (4 * g);
            int sl = tg & 1;
            uint32_t a[4];
            a[0] = stg[r0 * 64 + 2 * jA + sl];
            a[1] = stg[(r0 + 8) * 64 + 2 * jA + sl];
            a[2] = stg[r0 * 64 + 2 * jB + sl];
            a[3] = stg[(r0 + 8) * 64 + 2 * jB + sl];
            #pragma unroll
            for (int nf2 = 0; nf2 < 2; nf2++)
                mma_tf32(s2[mf][nf2], a, bfr[nf2]);
        }
    }

    // ---- phase 4: K-partials P[row][cw*16 + kk] ----
    float* P = sm + SM_P;
    #pragma unroll
    for (int mf = 0; mf < 4; mf++) {
        #pragma unroll
        for (int nf2 = 0; nf2 < 2; nf2++) {
            int row = rb + mf * 16 + g;
            int kk0 = nf2 * 8 + 2 * tg;
            *(float2*)&P[row * PP + cw * 16 + kk0] =
                make_float2(s2[mf][nf2][0], s2[mf][nf2][1]);
            *(float2*)&P[(row + 8) * PP + cw * 16 + kk0] =
                make_float2(s2[mf][nf2][2], s2[mf][nf2][3]);
        }
    }
    __syncthreads();

    // ---- phase 5: reduce, softmax, coalesced stores (thread = half row) ----
    const int row  = tid >> 1;
    const int half = tid & 1;
    const int kb   = 8 * half;

    float sv[8];
    #pragma unroll
    for (int j = 0; j < 8; j += 2) {
        float2 p0 = *(float2*)&P[row * PP +  0 + kb + j];
        float2 p1 = *(float2*)&P[row * PP + 16 + kb + j];
        float2 p2 = *(float2*)&P[row * PP + 32 + kb + j];
        float2 p3 = *(float2*)&P[row * PP + 48 + kb + j];
        sv[j]     = p0.x + p1.x + p2.x + p3.x + b2s[kb + j];
        sv[j + 1] = p0.y + p1.y + p2.y + p3.y + b2s[kb + j + 1];
    }
    float m = sv[0];
    #pragma unroll
    for (int j = 1; j < 8; j++) m = fmaxf(m, sv[j]);
    m = fmaxf(m, __shfl_xor_sync(0xFFFFFFFFu, m, 1));
    float ssum = 0.f;
    #pragma unroll
    for (int j = 0; j < 8; j++) { sv[j] = __expf(sv[j] - m); ssum += sv[j]; }
    ssum += __shfl_xor_sync(0xFFFFFFFFu, ssum, 1);
    float inv = 1.f / ssum;
    #pragma unroll
    for (int j = 0; j < 8; j++) sv[j] *= inv;

    int gr = row_base + row;
    if (gr < N) {
        *(float4*)&C[(size_t)gr * KCL + kb]     =
            make_float4(sv[0], sv[1], sv[2], sv[3]);
        *(float4*)&C[(size_t)gr * KCL + kb + 4] =
            make_float4(sv[4], sv[5], sv[6], sv[7]);
        if (write_bf16) {
            __nv_bfloat162 h0 = __floats2bfloat162_rn(sv[0], sv[1]);
            __nv_bfloat162 h1 = __floats2bfloat162_rn(sv[2], sv[3]);
            __nv_bfloat162 h2 = __floats2bfloat162_rn(sv[4], sv[5]);
            __nv_bfloat162 h3 = __floats2bfloat162_rn(sv[6], sv[7]);
            uint4 u;
            u.x = *(uint32_t*)&h0; u.y = *(uint32_t*)&h1;
            u.z = *(uint32_t*)&h2; u.w = *(uint32_t*)&h3;
            g_Cb[(size_t)gr * 2 + half] = u;
        }
    }
}

__inline__ __device__ float warp_reduce_sum(float v) {
    #pragma unroll
    for (int o = 16; o > 0; o >>= 1)
        v += __shfl_xor_sync(0xFFFFFFFFu, v, o);
    return v;
}

__device__ __forceinline__ float bf16x8_dot(uint4 a, uint4 b) {
    float2 fa, fb;
    float s = 0.f;
    fa = __bfloat1622float2(*(__nv_bfloat162*)&a.x);
    fb = __bfloat1622float2(*(__nv_bfloat162*)&b.x);
    s += fa.x * fb.x + fa.y * fb.y;
    fa = __bfloat1622float2(*(__nv_bfloat162*)&a.y);
    fb = __bfloat1622float2(*(__nv_bfloat162*)&b.y);
    s += fa.x * fb.x + fa.y * fb.y;
    fa = __bfloat1622float2(*(__nv_bfloat162*)&a.z);
    fb = __bfloat1622float2(*(__nv_bfloat162*)&b.z);
    s += fa.x * fb.x + fa.y * fb.y;
    fa = __bfloat1622float2(*(__nv_bfloat162*)&a.w);
    fb = __bfloat1622float2(*(__nv_bfloat162*)&b.w);
    s += fa.x * fb.x + fa.y * fb.y;
    return s;
}

// edge gather + reduce + (last block) finalize; dtype probe integrated
__global__ __launch_bounds__(256)
void edge_sum_kernel(const void* __restrict__ ei_raw,
                     const float* __restrict__ C,
                     int E, int N, int use_bf16,
                     float* __restrict__ out, int nk, int do_write)
{
    const int tid = threadIdx.x;
    // dtype probe: int64 -> all odd 32-bit words (high halves) are zero
    const int* ei32 = (const int*)ei_raw;
    int any = 0;
    #pragma unroll
    for (int s = 0; s < 2; s++) {
        long long j = ((long long)(tid * 2 + s) * E) >> 9;
        any |= ei32[2 * j + 1];
    }
    const int is64 = (__syncthreads_or(any) == 0);

    const int tid_g = blockIdx.x * blockDim.x + tid;
    const int total = gridDim.x * blockDim.x;
    float part = 0.f;

    if (use_bf16) {
        const uint4* Cb = (const uint4*)g_Cb;
        const int half = tid_g & 1;
        const int p0 = tid_g >> 1;
        const int np = total >> 1;
        if (is64) {
            const long long* ei = (const long long*)ei_raw;
            for (int e = p0; e < E; e += np) {
                int u = (int)ei[e];
                int v = (int)ei[(size_t)E + e];
                u = ((unsigned)u < (unsigned)N) ? u : 0;
                v = ((unsigned)v < (unsigned)N) ? v : 0;
                uint4 a = __ldg(&Cb[(size_t)u * 2 + half]);
                uint4 b = __ldg(&Cb[(size_t)v * 2 + half]);
                part += bf16x8_dot(a, b);
            }
        } else {
            for (int e = p0; e < E; e += np) {
                int u = ei32[e];
                int v = ei32[(size_t)E + e];
                u = ((unsigned)u < (unsigned)N) ? u : 0;
                v = ((unsigned)v < (unsigned)N) ? v : 0;
                uint4 a = __ldg(&Cb[(size_t)u * 2 + half]);
                uint4 b = __ldg(&Cb[(size_t)v * 2 + half]);
                part += bf16x8_dot(a, b);
            }
        }
    } else {
        const int lane4 = tid_g & 3;
        const int q0 = tid_g >> 2;
        const int nq = total >> 2;
        const float4* C4 = (const float4*)C;
        if (is64) {
            const long long* ei = (const long long*)ei_raw;
            for (int e = q0; e < E; e += nq) {
                int u = (int)ei[e];
                int v = (int)ei[(size_t)E + e];
                u = ((unsigned)u < (unsigned)N) ? u : 0;
                v = ((unsigned)v < (unsigned)N) ? v : 0;
                float4 a = __ldg(&C4[(size_t)u * 4 + lane4]);
                float4 b = __ldg(&C4[(size_t)v * 4 + lane4]);
                part += a.x * b.x + a.y * b.y + a.z * b.z + a.w * b.w;
            }
        } else {
            for (int e = q0; e < E; e += nq) {
                int u = ei32[e];
                int v = ei32[(size_t)E + e];
                u = ((unsigned)u < (unsigned)N) ? u : 0;
                v = ((unsigned)v < (unsigned)N) ? v : 0;
                float4 a = __ldg(&C4[(size_t)u * 4 + lane4]);
                float4 b = __ldg(&C4[(size_t)v * 4 + lane4]);
                part += a.x * b.x + a.y * b.y + a.z * b.z + a.w * b.w;
            }
        }
    }

    part = warp_reduce_sum(part);
    __shared__ float ws[8];
    int lane = tid & 31, wrp = tid >> 5;
    if (lane == 0) ws[wrp] = part;
    __syncthreads();
    if (tid == 0) {
        float v = 0.f;
        #pragma unroll
        for (int w = 0; w < 8; w++) v += ws[w];
        atomicAdd(&g_edge_sum, v);
        __threadfence();
        int t = atomicAdd(&g_done, 1);
        if (t == gridDim.x - 1) {          // last block: finalize + reset
            if (do_write) out[nk] = -g_edge_sum / (float)E;
            g_edge_sum = 0.f;
            g_done = 0;
        }
    }
}

extern "C" void kernel_launch(void* const* d_in, const int* in_sizes, int n_in,
                              void* d_out, int out_size)
{
    const float* x  = (const float*)d_in[0];
    const void*  ei = d_in[1];
    const float* W1 = (const float*)d_in[2];
    const float* b1 = (const float*)d_in[3];
    const float* W2 = (const float*)d_in[4];
    const float* b2 = (const float*)d_in[5];
    float* out = (float*)d_out;

    const int N = in_sizes[0] / D_IN;
    const int E = in_sizes[1] / 2;
    const int use_bf16 = (N <= CB_CAP) ? 1 : 0;
    const int nk = N * KCL;

    cudaFuncSetAttribute(fused_mlp_softmax,
                         cudaFuncAttributeMaxDynamicSharedMemorySize, SMEM_BYTES);

    const int ntiles = (N + TM - 1) / TM;
    fused_mlp_softmax<<<ntiles, NT, SMEM_BYTES>>>(x, W1, b1, W2, b2, out, N, use_bf16);

    edge_sum_kernel<<<1184, 256>>>(ei, out, E, N, use_bf16,
                                   out, nk, out_size > nk ? 1 : 0);
}

// round 6
// speedup vs baseline: 4.3886x; 1.6167x over previous
#include <cuda_runtime.h>
#include <cuda_fp16.h>
#include <cuda_bf16.h>
#include <cstdint>

#define D_IN 128
#define D_H  256
#define KCL  16
#define TM   64
#define NT   256

// ---- smem layout (32-bit word offsets) ----
#define SM_XS  0                       // xs  [64][68]  fp16x2 kpairs
#define SM_W1  (64 * 68)               // W1h [256][68] fp16x2 (n-major, kpair cols)
#define SM_W2  (SM_W1 + 256 * 68)      // W2h [16][132] fp16x2
#define SM_B1  (SM_W2 + 16 * 132)      // b1  [256] fp32
#define SM_B2  (SM_B1 + 256)           // b2  [16]  fp32
#define SM_TOT (SM_B2 + 16)            // 24144 words
#define SMEM_BYTES (SM_TOT * 4)        // 96576 B  -> 2 CTAs/SM

// overlay after phase 1 (within xs+W1h region, W2h/b1/b2 stay live)
#define SM_STG 0                       // 8 warps x [32][36] = 9216 words
#define SM_P   9216                    // P [64][66] fp32 = 4224 words (ends 13440)
#define PP 66

#define CB_CAP 131072
__device__ uint4    g_Cb[CB_CAP * 2];      // bf16 copy of C (32 B/row)
__device__ uint32_t g_W1h[256 * 68];       // prepacked fp16x2 W1, padded pitch 68
__device__ uint32_t g_W2h[16 * 132];       // prepacked fp16x2 W2, padded pitch 132
__device__ float    g_edge_sum;
__device__ int      g_done;

__device__ __forceinline__ uint32_t pack_h2(float a, float b) {
    __half2 h = __floats2half2_rn(a, b);
    return *(uint32_t*)&h;
}

__device__ __forceinline__ void mma_f16(float* d, const uint32_t* a, const uint32_t* b) {
    asm volatile(
        "mma.sync.aligned.m16n8k16.row.col.f32.f16.f16.f32 "
        "{%0,%1,%2,%3}, {%4,%5,%6,%7}, {%8,%9}, {%0,%1,%2,%3};"
        : "+f"(d[0]), "+f"(d[1]), "+f"(d[2]), "+f"(d[3])
        : "r"(a[0]), "r"(a[1]), "r"(a[2]), "r"(a[3]), "r"(b[0]), "r"(b[1]));
}

// one-time weight repack: W1h[n][kp] = {W1[2kp][n], W1[2kp+1][n]} etc.
__global__ void prep_kernel(const float* __restrict__ W1, const float* __restrict__ W2)
{
    int idx = blockIdx.x * blockDim.x + threadIdx.x;
    if (idx < 256 * 64) {
        int n = idx & 255, kp = idx >> 8;
        g_W1h[n * 68 + kp] = pack_h2(W1[(2 * kp) * D_H + n], W1[(2 * kp + 1) * D_H + n]);
    } else {
        idx -= 256 * 64;
        if (idx < 16 * 128) {
            int kk = idx & 15, kp = idx >> 4;
            g_W2h[kk * 132 + kp] = pack_h2(W2[(2 * kp) * KCL + kk], W2[(2 * kp + 1) * KCL + kk]);
        }
    }
}

__global__ __launch_bounds__(NT, 2)
void fused_mlp_softmax(const float* __restrict__ x,
                       const float* __restrict__ b1,
                       const float* __restrict__ b2,
                       float* __restrict__ C,
                       int N, int write_bf16)
{
    extern __shared__ float smf[];
    uint32_t* smw = (uint32_t*)smf;
    uint32_t* xs  = smw + SM_XS;
    uint32_t* W1s = smw + SM_W1;
    uint32_t* W2s = smw + SM_W2;
    float* b1s = smf + SM_B1;
    float* b2s = smf + SM_B2;

    const int tid = threadIdx.x;
    const int row_base = blockIdx.x * TM;

    // ---- phase 0: stage weights (prepacked) + x tile (pack to fp16x2) ----
    {
        const uint4* src = (const uint4*)g_W1h;
        uint4* dst = (uint4*)W1s;
        #pragma unroll 4
        for (int i = tid; i < (256 * 68) / 4; i += NT) dst[i] = src[i];
    }
    {
        const uint4* src = (const uint4*)g_W2h;
        uint4* dst = (uint4*)W2s;
        for (int i = tid; i < (16 * 132) / 4; i += NT) dst[i] = src[i];
    }
    b1s[tid] = b1[tid];                 // NT == D_H
    if (tid < KCL) b2s[tid] = b2[tid];
    {
        const float4* xv = (const float4*)x;
        #pragma unroll
        for (int i = tid; i < TM * (D_IN / 4); i += NT) {
            int r = i >> 5, c4 = i & 31;
            int gr = row_base + r;
            float4 v = make_float4(0.f, 0.f, 0.f, 0.f);
            if (gr < N) v = xv[(size_t)gr * (D_IN / 4) + c4];
            uint2 u;
            u.x = pack_h2(v.x, v.y);
            u.y = pack_h2(v.z, v.w);
            *(uint2*)&xs[r * 68 + 2 * c4] = u;
        }
    }
    __syncthreads();

    // ---- phase 1: layer 1 fp16 mma, 8 warps, warp tile 32x64 ----
    const int wid = tid >> 5, lane = tid & 31;
    const int g = lane >> 2, tg = lane & 3;
    const int rw = wid >> 2, cw = wid & 3;
    const int rb = rw * 32, nb = cw * 64;

    float acc[2][8][4];
    #pragma unroll
    for (int mf = 0; mf < 2; mf++)
        #pragma unroll
        for (int nf = 0; nf < 8; nf++)
            #pragma unroll
            for (int q = 0; q < 4; q++) acc[mf][nf][q] = 0.f;

    #pragma unroll 1
    for (int ks = 0; ks < 8; ks++) {
        const int kp0 = 8 * ks + tg;
        uint32_t a[2][4];
        #pragma unroll
        for (int mf = 0; mf < 2; mf++) {
            int r0 = rb + mf * 16 + g;
            a[mf][0] = xs[r0 * 68 + kp0];
            a[mf][1] = xs[(r0 + 8) * 68 + kp0];
            a[mf][2] = xs[r0 * 68 + kp0 + 4];
            a[mf][3] = xs[(r0 + 8) * 68 + kp0 + 4];
        }
        uint32_t b[8][2];
        #pragma unroll
        for (int nf = 0; nf < 8; nf++) {
            int n = nb + nf * 8 + g;
            b[nf][0] = W1s[n * 68 + kp0];
            b[nf][1] = W1s[n * 68 + kp0 + 4];
        }
        #pragma unroll
        for (int mf = 0; mf < 2; mf++)
            #pragma unroll
            for (int nf = 0; nf < 8; nf++)
                mma_f16(acc[mf][nf], a[mf], b[nf]);
    }
    __syncthreads();   // xs/W1s dead; overlay begins

    // ---- phase 2: bias+relu -> fp16x2 -> warp-local staging [32][36] ----
    uint32_t* stg = smw + SM_STG + wid * 1152;
    #pragma unroll
    for (int mf = 0; mf < 2; mf++) {
        #pragma unroll
        for (int nf = 0; nf < 8; nf++) {
            int col = nb + nf * 8 + 2 * tg;
            float bc0 = b1s[col], bc1 = b1s[col + 1];
            int row = mf * 16 + g;
            int kp = 4 * nf + tg;
            stg[row * 36 + kp] = pack_h2(fmaxf(acc[mf][nf][0] + bc0, 0.f),
                                         fmaxf(acc[mf][nf][1] + bc1, 0.f));
            stg[(row + 8) * 36 + kp] = pack_h2(fmaxf(acc[mf][nf][2] + bc0, 0.f),
                                               fmaxf(acc[mf][nf][3] + bc1, 0.f));
        }
    }
    __syncwarp();

    // ---- phase 3: layer 2 fp16 mma: per warp M=32, N=16, K=64 (slice cw) ----
    float s2[2][2][4];
    #pragma unroll
    for (int mf = 0; mf < 2; mf++)
        #pragma unroll
        for (int nf2 = 0; nf2 < 2; nf2++)
            #pragma unroll
            for (int q = 0; q < 4; q++) s2[mf][nf2][q] = 0.f;

    const int kbase = nb >> 1;   // this warp's kpair offset into D_H
    #pragma unroll
    for (int ks = 0; ks < 4; ks++) {
        const int kp0 = 8 * ks + tg;
        uint32_t bb[2][2];
        #pragma unroll
        for (int nf2 = 0; nf2 < 2; nf2++) {
            int n = nf2 * 8 + g;
            bb[nf2][0] = W2s[n * 132 + kbase + kp0];
            bb[nf2][1] = W2s[n * 132 + kbase + kp0 + 4];
        }
        #pragma unroll
        for (int mf = 0; mf < 2; mf++) {
            int r0 = mf * 16 + g;
            uint32_t a[4];
            a[0] = stg[r0 * 36 + kp0];
            a[1] = stg[(r0 + 8) * 36 + kp0];
            a[2] = stg[r0 * 36 + kp0 + 4];
            a[3] = stg[(r0 + 8) * 36 + kp0 + 4];
            #pragma unroll
            for (int nf2 = 0; nf2 < 2; nf2++)
                mma_f16(s2[mf][nf2], a, bb[nf2]);
        }
    }

    // ---- phase 4: K-partials P[row][cw*16 + kk] ----
    float* P = smf + SM_P;
    #pragma unroll
    for (int mf = 0; mf < 2; mf++) {
        #pragma unroll
        for (int nf2 = 0; nf2 < 2; nf2++) {
            int row = rb + mf * 16 + g;
            int kk0 = nf2 * 8 + 2 * tg;
            *(float2*)&P[row * PP + cw * 16 + kk0] =
                make_float2(s2[mf][nf2][0], s2[mf][nf2][1]);
            *(float2*)&P[(row + 8) * PP + cw * 16 + kk0] =
                make_float2(s2[mf][nf2][2], s2[mf][nf2][3]);
        }
    }
    __syncthreads();

    // ---- phase 5: reduce, softmax (4-lane segments), coalesced stores ----
    const int row = tid >> 2;
    const int q   = tid & 3;
    const int kb  = 4 * q;

    float sv[4];
    #pragma unroll
    for (int j = 0; j < 4; j++) sv[j] = b2s[kb + j];
    #pragma unroll
    for (int c = 0; c < 4; c++) {
        float2 pA = *(float2*)&P[row * PP + 16 * c + kb];
        float2 pB = *(float2*)&P[row * PP + 16 * c + kb + 2];
        sv[0] += pA.x; sv[1] += pA.y; sv[2] += pB.x; sv[3] += pB.y;
    }
    float m = fmaxf(fmaxf(sv[0], sv[1]), fmaxf(sv[2], sv[3]));
    m = fmaxf(m, __shfl_xor_sync(0xFFFFFFFFu, m, 1, 4));
    m = fmaxf(m, __shfl_xor_sync(0xFFFFFFFFu, m, 2, 4));
    float ssum = 0.f;
    #pragma unroll
    for (int j = 0; j < 4; j++) { sv[j] = __expf(sv[j] - m); ssum += sv[j]; }
    ssum += __shfl_xor_sync(0xFFFFFFFFu, ssum, 1, 4);
    ssum += __shfl_xor_sync(0xFFFFFFFFu, ssum, 2, 4);
    float inv = 1.f / ssum;
    #pragma unroll
    for (int j = 0; j < 4; j++) sv[j] *= inv;

    int gr = row_base + row;
    if (gr < N) {
        *(float4*)&C[(size_t)gr * KCL + kb] = make_float4(sv[0], sv[1], sv[2], sv[3]);
        if (write_bf16) {
            __nv_bfloat162 h0 = __floats2bfloat162_rn(sv[0], sv[1]);
            __nv_bfloat162 h1 = __floats2bfloat162_rn(sv[2], sv[3]);
            uint2 u;
            u.x = *(uint32_t*)&h0;
            u.y = *(uint32_t*)&h1;
            ((uint2*)g_Cb)[(size_t)gr * 4 + q] = u;
        }
    }
}

__inline__ __device__ float warp_reduce_sum(float v) {
    #pragma unroll
    for (int o = 16; o > 0; o >>= 1)
        v += __shfl_xor_sync(0xFFFFFFFFu, v, o);
    return v;
}

__device__ __forceinline__ float bf16x8_dot(uint4 a, uint4 b) {
    float2 fa, fb;
    float s = 0.f;
    fa = __bfloat1622float2(*(__nv_bfloat162*)&a.x);
    fb = __bfloat1622float2(*(__nv_bfloat162*)&b.x);
    s += fa.x * fb.x + fa.y * fb.y;
    fa = __bfloat1622float2(*(__nv_bfloat162*)&a.y);
    fb = __bfloat1622float2(*(__nv_bfloat162*)&b.y);
    s += fa.x * fb.x + fa.y * fb.y;
    fa = __bfloat1622float2(*(__nv_bfloat162*)&a.z);
    fb = __bfloat1622float2(*(__nv_bfloat162*)&b.z);
    s += fa.x * fb.x + fa.y * fb.y;
    fa = __bfloat1622float2(*(__nv_bfloat162*)&a.w);
    fb = __bfloat1622float2(*(__nv_bfloat162*)&b.w);
    s += fa.x * fb.x + fa.y * fb.y;
    return s;
}

// edge gather + reduce + (last block) finalize; dtype probe integrated
__global__ __launch_bounds__(256)
void edge_sum_kernel(const void* __restrict__ ei_raw,
                     const float* __restrict__ C,
                     int E, int N, int use_bf16,
                     float* __restrict__ out, int nk, int do_write)
{
    const int tid = threadIdx.x;
    const int* ei32 = (const int*)ei_raw;
    int any = 0;
    #pragma unroll
    for (int s = 0; s < 2; s++) {
        long long j = ((long long)(tid * 2 + s) * E) >> 9;
        any |= ei32[2 * j + 1];
    }
    const int is64 = (__syncthreads_or(any) == 0);

    const int tid_g = blockIdx.x * blockDim.x + tid;
    const int total = gridDim.x * blockDim.x;
    float part = 0.f;

    if (use_bf16) {
        const uint4* Cb = (const uint4*)g_Cb;
        const int half = tid_g & 1;
        const int p0 = tid_g >> 1;
        const int np = total >> 1;
        if (is64) {
            const long long* ei = (const long long*)ei_raw;
            for (int e = p0; e < E; e += np) {
                int u = (int)ei[e];
                int v = (int)ei[(size_t)E + e];
                u = ((unsigned)u < (unsigned)N) ? u : 0;
                v = ((unsigned)v < (unsigned)N) ? v : 0;
                uint4 a = __ldg(&Cb[(size_t)u * 2 + half]);
                uint4 b = __ldg(&Cb[(size_t)v * 2 + half]);
                part += bf16x8_dot(a, b);
            }
        } else {
            for (int e = p0; e < E; e += np) {
                int u = ei32[e];
                int v = ei32[(size_t)E + e];
                u = ((unsigned)u < (unsigned)N) ? u : 0;
                v = ((unsigned)v < (unsigned)N) ? v : 0;
                uint4 a = __ldg(&Cb[(size_t)u * 2 + half]);
                uint4 b = __ldg(&Cb[(size_t)v * 2 + half]);
                part += bf16x8_dot(a, b);
            }
        }
    } else {
        const int lane4 = tid_g & 3;
        const int q0 = tid_g >> 2;
        const int nq = total >> 2;
        const float4* C4 = (const float4*)C;
        if (is64) {
            const long long* ei = (const long long*)ei_raw;
            for (int e = q0; e < E; e += nq) {
                int u = (int)ei[e];
                int v = (int)ei[(size_t)E + e];
                u = ((unsigned)u < (unsigned)N) ? u : 0;
                v = ((unsigned)v < (unsigned)N) ? v : 0;
                float4 a = __ldg(&C4[(size_t)u * 4 + lane4]);
                float4 b = __ldg(&C4[(size_t)v * 4 + lane4]);
                part += a.x * b.x + a.y * b.y + a.z * b.z + a.w * b.w;
            }
        } else {
            for (int e = q0; e < E; e += nq) {
                int u = ei32[e];
                int v = ei32[(size_t)E + e];
                u = ((unsigned)u < (unsigned)N) ? u : 0;
                v = ((unsigned)v < (unsigned)N) ? v : 0;
                float4 a = __ldg(&C4[(size_t)u * 4 + lane4]);
                float4 b = __ldg(&C4[(size_t)v * 4 + lane4]);
                part += a.x * b.x + a.y * b.y + a.z * b.z + a.w * b.w;
            }
        }
    }

    part = warp_reduce_sum(part);
    __shared__ float ws[8];
    int lane = tid & 31, wrp = tid >> 5;
    if (lane == 0) ws[wrp] = part;
    __syncthreads();
    if (tid == 0) {
        float v = 0.f;
        #pragma unroll
        for (int w = 0; w < 8; w++) v += ws[w];
        atomicAdd(&g_edge_sum, v);
        __threadfence();
        int t = atomicAdd(&g_done, 1);
        if (t == gridDim.x - 1) {
            if (do_write) out[nk] = -g_edge_sum / (float)E;
            g_edge_sum = 0.f;
            g_done = 0;
        }
    }
}

extern "C" void kernel_launch(void* const* d_in, const int* in_sizes, int n_in,
                              void* d_out, int out_size)
{
    const float* x  = (const float*)d_in[0];
    const void*  ei = d_in[1];
    const float* W1 = (const float*)d_in[2];
    const float* b1 = (const float*)d_in[3];
    const float* W2 = (const float*)d_in[4];
    const float* b2 = (const float*)d_in[5];
    float* out = (float*)d_out;

    const int N = in_sizes[0] / D_IN;
    const int E = in_sizes[1] / 2;
    const int use_bf16 = (N <= CB_CAP) ? 1 : 0;
    const int nk = N * KCL;

    cudaFuncSetAttribute(fused_mlp_softmax,
                         cudaFuncAttributeMaxDynamicSharedMemorySize, SMEM_BYTES);

    prep_kernel<<<72, 256>>>(W1, W2);

    const int ntiles = (N + TM - 1) / TM;
    fused_mlp_softmax<<<ntiles, NT, SMEM_BYTES>>>(x, b1, b2, out, N, use_bf16);

    edge_sum_kernel<<<1184, 256>>>(ei, out, E, N, use_bf16,
                                   out, nk, out_size > nk ? 1 : 0);
}

// round 7
// speedup vs baseline: 4.5833x; 1.0444x over previous
#include <cuda_runtime.h>
#include <cuda_fp16.h>
#include <cuda_bf16.h>
#include <cstdint>

#define D_IN 128
#define D_H  256
#define KCL  16
#define TM   64
#define NT   256

// ---- smem layout (32-bit word offsets) ----
#define SM_XS  0                       // xs  [64][68]  fp16x2 kpairs
#define SM_W1  (64 * 68)               // W1h [256][68] fp16x2 (n-major, kpair cols)
#define SM_W2  (SM_W1 + 256 * 68)      // W2h [16][132] fp16x2
#define SM_B1  (SM_W2 + 16 * 132)      // b1  [256] fp32
#define SM_B2  (SM_B1 + 256)           // b2  [16]  fp32
#define SM_TOT (SM_B2 + 16)            // 24144 words
#define SMEM_BYTES (SM_TOT * 4)        // 96576 B  -> 2 CTAs/SM

// overlay after phase 1 (inside xs+W1 region? NO - only inside xs..: stg+P sit
// in words 0..13440, which spans xs [0..4352) and the LOW part of W1h.
// W1h must stay live across tiles -> move overlay entirely into xs + a
// dedicated scratch region instead:
//   stg: 8 warps x [32][36] = 9216 words, P: [64][66] = 4224 words
// xs is only 4352 words, so we append scratch after SM_TOT.
#define SM_STG SM_TOT                  // 9216 words
#define SM_P   (SM_TOT + 9216)         // 4224 words
#define SM_ALL (SM_P + 4224)           // 37584 words = 150336 B... too big for 2/SM?
// 150336*2 = 300KB > 227KB. Instead: stg overlays xs (4352) + P after SM_TOT.
// stg needs 9216 > 4352. Shrink stg: store only kpairs actually needed:
// per warp [32][36] = 1152 words; overlay stg into xs region per 4 warps is not enough.
// Resolution: put stg at SM_TOT (9216 words) and P overlaying xs (4224 <= 4352).
#undef SM_STG
#undef SM_P
#undef SM_ALL
#define SM_P   0                       // P [64][66] overlays xs (4224 <= 4352 words)
#define SM_STG SM_TOT                  // stg after everything: 9216 words
#define SM_ALL (SM_TOT + 9216)         // 33360 words = 133440 B -> 2 CTAs/SM? 266KB > 227KB!
#define PP 66

#define CB_CAP 131072
__device__ uint4 g_Cb[CB_CAP * 2];     // bf16 copy of C (32 B/row)
__device__ float g_edge_sum;
__device__ int   g_done;

__device__ __forceinline__ uint32_t pack_h2(float a, float b) {
    __half2 h = __floats2half2_rn(a, b);
    return *(uint32_t*)&h;
}

__device__ __forceinline__ void mma_f16(float* d, const uint32_t* a, const uint32_t* b) {
    asm volatile(
        "mma.sync.aligned.m16n8k16.row.col.f32.f16.f16.f32 "
        "{%0,%1,%2,%3}, {%4,%5,%6,%7}, {%8,%9}, {%0,%1,%2,%3};"
        : "+f"(d[0]), "+f"(d[1]), "+f"(d[2]), "+f"(d[3])
        : "r"(a[0]), "r"(a[1]), "r"(a[2]), "r"(a[3]), "r"(b[0]), "r"(b[1]));
}

// Persistent fused MLP+softmax. Weights packed to smem once; loop over tiles.
// stg is folded into registers: phase-2/3 are fused per-warp without a
// staging round-trip for the A operand of layer 2. Each thread already holds
// acc[2][8][4] = its 32x64 slice of h in exactly the m16n8k16 A-fragment
// layout needed for layer 2 IF we reinterpret (nf, quad) as K. For layer 2,
// thread needs A-frags a[0..3] = h2{k=kp0*2}, rows r0/r0+8 — which live in
// OTHER lanes' acc registers. We exchange via the small xs region instead
// (4352 words): per warp slice of 544 words, [32 rows][17 kpair cols] chunked
// over 2 column-halves. To keep it simple and within smem, stg uses the xs
// region in two half-K passes (kpairs 0..15, then 16..31).
#define STGP 17
__global__ __launch_bounds__(NT, 2)
void fused_mlp_softmax(const float* __restrict__ x,
                       const float* __restrict__ W1,
                       const float* __restrict__ b1,
                       const float* __restrict__ W2,
                       const float* __restrict__ b2,
                       float* __restrict__ C,
                       int N, int ntiles, int write_bf16)
{
    extern __shared__ float smf[];
    uint32_t* smw = (uint32_t*)smf;
    uint32_t* xs  = smw + SM_XS;
    uint32_t* W1s = smw + SM_W1;
    uint32_t* W2s = smw + SM_W2;
    float* b1s = smf + SM_B1;
    float* b2s = smf + SM_B2;

    const int tid = threadIdx.x;
    const int wid = tid >> 5, lane = tid & 31;
    const int g = lane >> 2, tg = lane & 3;
    const int rw = wid >> 2, cw = wid & 3;
    const int rb = rw * 32, nb = cw * 64;

    // ---- once: pack W1 [k][n] fp32 -> W1s [n][kp] fp16x2 ----
    for (int i = tid; i < 256 * 64; i += NT) {
        int n = i & 255, kp = i >> 8;
        W1s[n * 68 + kp] = pack_h2(W1[(2 * kp) * D_H + n], W1[(2 * kp + 1) * D_H + n]);
    }
    for (int i = tid; i < 16 * 128; i += NT) {
        int kk = i & 15, kp = i >> 4;
        W2s[kk * 132 + kp] = pack_h2(W2[(2 * kp) * KCL + kk], W2[(2 * kp + 1) * KCL + kk]);
    }
    b1s[tid] = b1[tid];
    if (tid < KCL) b2s[tid] = b2[tid];

    for (int tile = blockIdx.x; tile < ntiles; tile += gridDim.x) {
        const int row_base = tile * TM;

        // ---- phase 0: x tile -> fp16x2 smem ----
        {
            const float4* xv = (const float4*)x;
            #pragma unroll
            for (int i = tid; i < TM * (D_IN / 4); i += NT) {
                int r = i >> 5, c4 = i & 31;
                int gr = row_base + r;
                float4 v = make_float4(0.f, 0.f, 0.f, 0.f);
                if (gr < N) v = xv[(size_t)gr * (D_IN / 4) + c4];
                uint2 u;
                u.x = pack_h2(v.x, v.y);
                u.y = pack_h2(v.z, v.w);
                *(uint2*)&xs[r * 68 + 2 * c4] = u;
            }
        }
        __syncthreads();

        // ---- phase 1: layer 1 fp16 mma, warp tile 32x64 ----
        float acc[2][8][4];
        #pragma unroll
        for (int mf = 0; mf < 2; mf++)
            #pragma unroll
            for (int nf = 0; nf < 8; nf++)
                #pragma unroll
                for (int q = 0; q < 4; q++) acc[mf][nf][q] = 0.f;

        #pragma unroll 1
        for (int ks = 0; ks < 8; ks++) {
            const int kp0 = 8 * ks + tg;
            uint32_t a[2][4];
            #pragma unroll
            for (int mf = 0; mf < 2; mf++) {
                int r0 = rb + mf * 16 + g;
                a[mf][0] = xs[r0 * 68 + kp0];
                a[mf][1] = xs[(r0 + 8) * 68 + kp0];
                a[mf][2] = xs[r0 * 68 + kp0 + 4];
                a[mf][3] = xs[(r0 + 8) * 68 + kp0 + 4];
            }
            uint32_t b[8][2];
            #pragma unroll
            for (int nf = 0; nf < 8; nf++) {
                int n = nb + nf * 8 + g;
                b[nf][0] = W1s[n * 68 + kp0];
                b[nf][1] = W1s[n * 68 + kp0 + 4];
            }
            #pragma unroll
            for (int mf = 0; mf < 2; mf++)
                #pragma unroll
                for (int nf = 0; nf < 8; nf++)
                    mma_f16(acc[mf][nf], a[mf], b[nf]);
        }
        __syncthreads();   // xs dead; reuse as stg/P

        // ---- phase 2+3 fused, two half-K passes through xs region ----
        // pass p covers this warp's h columns [nb + 32p, nb + 32p + 32):
        // stg slice per warp: [32 rows][17 kpairs] at xs + wid*544 + p-phase reuse
        float s2[2][2][4];
        #pragma unroll
        for (int mf = 0; mf < 2; mf++)
            #pragma unroll
            for (int nf2 = 0; nf2 < 2; nf2++)
                #pragma unroll
                for (int q = 0; q < 4; q++) s2[mf][nf2][q] = 0.f;

        uint32_t* stg = xs + wid * 544;   // 8*544 = 4352 words, fits xs exactly
        #pragma unroll
        for (int p = 0; p < 2; p++) {
            // stage h[rows 0..31][kpairs 16p..16p+16) as fp16x2
            #pragma unroll
            for (int mf = 0; mf < 2; mf++) {
                #pragma unroll
                for (int nf = 4 * p; nf < 4 * p + 4; nf++) {
                    int col = nb + nf * 8 + 2 * tg;
                    float bc0 = b1s[col], bc1 = b1s[col + 1];
                    int row = mf * 16 + g;
                    int kp = (4 * nf + tg) & 15;
                    stg[row * STGP + kp] = pack_h2(fmaxf(acc[mf][nf][0] + bc0, 0.f),
                                                   fmaxf(acc[mf][nf][1] + bc1, 0.f));
                    stg[(row + 8) * STGP + kp] = pack_h2(fmaxf(acc[mf][nf][2] + bc0, 0.f),
                                                         fmaxf(acc[mf][nf][3] + bc1, 0.f));
                }
            }
            __syncwarp();
            // consume: layer-2 mma over this 32-wide K slice (2 k-steps)
            const int kbase = (nb >> 1) + 16 * p;   // global kpair offset
            #pragma unroll
            for (int ks = 0; ks < 2; ks++) {
                const int kp0 = 8 * ks + tg;
                uint32_t bb[2][2];
                #pragma unroll
                for (int nf2 = 0; nf2 < 2; nf2++) {
                    int n = nf2 * 8 + g;
                    bb[nf2][0] = W2s[n * 132 + kbase + kp0];
                    bb[nf2][1] = W2s[n * 132 + kbase + kp0 + 4];
                }
                #pragma unroll
                for (int mf = 0; mf < 2; mf++) {
                    int r0 = mf * 16 + g;
                    uint32_t a[4];
                    a[0] = stg[r0 * STGP + kp0];
                    a[1] = stg[(r0 + 8) * STGP + kp0];
                    a[2] = stg[r0 * STGP + kp0 + 4];
                    a[3] = stg[(r0 + 8) * STGP + kp0 + 4];
                    #pragma unroll
                    for (int nf2 = 0; nf2 < 2; nf2++)
                        mma_f16(s2[mf][nf2], a, bb[nf2]);
                }
            }
            __syncwarp();
        }
        __syncthreads();   // stg (xs region) dead; reuse as P

        // ---- phase 4: K-partials P[row][cw*16 + kk] (P overlays xs) ----
        float* P = (float*)xs;
        #pragma unroll
        for (int mf = 0; mf < 2; mf++) {
            #pragma unroll
            for (int nf2 = 0; nf2 < 2; nf2++) {
                int row = rb + mf * 16 + g;
                int kk0 = nf2 * 8 + 2 * tg;
                *(float2*)&P[row * PP + cw * 16 + kk0] =
                    make_float2(s2[mf][nf2][0], s2[mf][nf2][1]);
                *(float2*)&P[(row + 8) * PP + cw * 16 + kk0] =
                    make_float2(s2[mf][nf2][2], s2[mf][nf2][3]);
            }
        }
        __syncthreads();

        // ---- phase 5: reduce, softmax (4-lane segments), coalesced stores ----
        {
            const int row = tid >> 2;
            const int q   = tid & 3;
            const int kb  = 4 * q;

            float sv[4];
            #pragma unroll
            for (int j = 0; j < 4; j++) sv[j] = b2s[kb + j];
            #pragma unroll
            for (int c = 0; c < 4; c++) {
                float2 pA = *(float2*)&P[row * PP + 16 * c + kb];
                float2 pB = *(float2*)&P[row * PP + 16 * c + kb + 2];
                sv[0] += pA.x; sv[1] += pA.y; sv[2] += pB.x; sv[3] += pB.y;
            }
            float m = fmaxf(fmaxf(sv[0], sv[1]), fmaxf(sv[2], sv[3]));
            m = fmaxf(m, __shfl_xor_sync(0xFFFFFFFFu, m, 1, 4));
            m = fmaxf(m, __shfl_xor_sync(0xFFFFFFFFu, m, 2, 4));
            float ssum = 0.f;
            #pragma unroll
            for (int j = 0; j < 4; j++) { sv[j] = __expf(sv[j] - m); ssum += sv[j]; }
            ssum += __shfl_xor_sync(0xFFFFFFFFu, ssum, 1, 4);
            ssum += __shfl_xor_sync(0xFFFFFFFFu, ssum, 2, 4);
            float inv = 1.f / ssum;
            #pragma unroll
            for (int j = 0; j < 4; j++) sv[j] *= inv;

            int gr = row_base + row;
            if (gr < N) {
                *(float4*)&C[(size_t)gr * KCL + kb] =
                    make_float4(sv[0], sv[1], sv[2], sv[3]);
                if (write_bf16) {
                    __nv_bfloat162 h0 = __floats2bfloat162_rn(sv[0], sv[1]);
                    __nv_bfloat162 h1 = __floats2bfloat162_rn(sv[2], sv[3]);
                    uint2 u;
                    u.x = *(uint32_t*)&h0;
                    u.y = *(uint32_t*)&h1;
                    ((uint2*)g_Cb)[(size_t)gr * 4 + q] = u;
                }
            }
        }
        __syncthreads();   // P (xs region) dead before next tile's xs writes
    }
}

__inline__ __device__ float warp_reduce_sum(float v) {
    #pragma unroll
    for (int o = 16; o > 0; o >>= 1)
        v += __shfl_xor_sync(0xFFFFFFFFu, v, o);
    return v;
}

__device__ __forceinline__ float bf16x8_dot(uint4 a, uint4 b) {
    float2 fa, fb;
    float s = 0.f;
    fa = __bfloat1622float2(*(__nv_bfloat162*)&a.x);
    fb = __bfloat1622float2(*(__nv_bfloat162*)&b.x);
    s += fa.x * fb.x + fa.y * fb.y;
    fa = __bfloat1622float2(*(__nv_bfloat162*)&a.y);
    fb = __bfloat1622float2(*(__nv_bfloat162*)&b.y);
    s += fa.x * fb.x + fa.y * fb.y;
    fa = __bfloat1622float2(*(__nv_bfloat162*)&a.z);
    fb = __bfloat1622float2(*(__nv_bfloat162*)&b.z);
    s += fa.x * fb.x + fa.y * fb.y;
    fa = __bfloat1622float2(*(__nv_bfloat162*)&a.w);
    fb = __bfloat1622float2(*(__nv_bfloat162*)&b.w);
    s += fa.x * fb.x + fa.y * fb.y;
    return s;
}

__global__ __launch_bounds__(256)
void edge_sum_kernel(const void* __restrict__ ei_raw,
                     const float* __restrict__ C,
                     int E, int N, int use_bf16,
                     float* __restrict__ out, int nk, int do_write)
{
    const int tid = threadIdx.x;
    const int* ei32 = (const int*)ei_raw;
    int any = 0;
    #pragma unroll
    for (int s = 0; s < 2; s++) {
        long long j = ((long long)(tid * 2 + s) * E) >> 9;
        any |= ei32[2 * j + 1];
    }
    const int is64 = (__syncthreads_or(any) == 0);

    const int tid_g = blockIdx.x * blockDim.x + tid;
    const int total = gridDim.x * blockDim.x;
    float part = 0.f;

    if (use_bf16) {
        const uint4* Cb = (const uint4*)g_Cb;
        const int half = tid_g & 1;
        const int p0 = tid_g >> 1;
        const int np = total >> 1;
        if (is64) {
            const long long* ei = (const long long*)ei_raw;
            for (int e = p0; e < E; e += np) {
                int u = (int)ei[e];
                int v = (int)ei[(size_t)E + e];
                u = ((unsigned)u < (unsigned)N) ? u : 0;
                v = ((unsigned)v < (unsigned)N) ? v : 0;
                uint4 a = __ldg(&Cb[(size_t)u * 2 + half]);
                uint4 b = __ldg(&Cb[(size_t)v * 2 + half]);
                part += bf16x8_dot(a, b);
            }
        } else {
            for (int e = p0; e < E; e += np) {
                int u = ei32[e];
                int v = ei32[(size_t)E + e];
                u = ((unsigned)u < (unsigned)N) ? u : 0;
                v = ((unsigned)v < (unsigned)N) ? v : 0;
                uint4 a = __ldg(&Cb[(size_t)u * 2 + half]);
                uint4 b = __ldg(&Cb[(size_t)v * 2 + half]);
                part += bf16x8_dot(a, b);
            }
        }
    } else {
        const int lane4 = tid_g & 3;
        const int q0 = tid_g >> 2;
        const int nq = total >> 2;
        const float4* C4 = (const float4*)C;
        if (is64) {
            const long long* ei = (const long long*)ei_raw;
            for (int e = q0; e < E; e += nq) {
                int u = (int)ei[e];
                int v = (int)ei[(size_t)E + e];
                u = ((unsigned)u < (unsigned)N) ? u : 0;
                v = ((unsigned)v < (unsigned)N) ? v : 0;
                float4 a = __ldg(&C4[(size_t)u * 4 + lane4]);
                float4 b = __ldg(&C4[(size_t)v * 4 + lane4]);
                part += a.x * b.x + a.y * b.y + a.z * b.z + a.w * b.w;
            }
        } else {
            for (int e = q0; e < E; e += nq) {
                int u = ei32[e];
                int v = ei32[(size_t)E + e];
                u = ((unsigned)u < (unsigned)N) ? u : 0;
                v = ((unsigned)v < (unsigned)N) ? v : 0;
                float4 a = __ldg(&C4[(size_t)u * 4 + lane4]);
                float4 b = __ldg(&C4[(size_t)v * 4 + lane4]);
                part += a.x * b.x + a.y * b.y + a.z * b.z + a.w * b.w;
            }
        }
    }

    part = warp_reduce_sum(part);
    __shared__ float ws[8];
    int lane = tid & 31, wrp = tid >> 5;
    if (lane == 0) ws[wrp] = part;
    __syncthreads();
    if (tid == 0) {
        float v = 0.f;
        #pragma unroll
        for (int w = 0; w < 8; w++) v += ws[w];
        atomicAdd(&g_edge_sum, v);
        __threadfence();
        int t = atomicAdd(&g_done, 1);
        if (t == gridDim.x - 1) {
            if (do_write) out[nk] = -g_edge_sum / (float)E;
            g_edge_sum = 0.f;
            g_done = 0;
        }
    }
}

extern "C" void kernel_launch(void* const* d_in, const int* in_sizes, int n_in,
                              void* d_out, int out_size)
{
    const float* x  = (const float*)d_in[0];
    const void*  ei = d_in[1];
    const float* W1 = (const float*)d_in[2];
    const float* b1 = (const float*)d_in[3];
    const float* W2 = (const float*)d_in[4];
    const float* b2 = (const float*)d_in[5];
    float* out = (float*)d_out;

    const int N = in_sizes[0] / D_IN;
    const int E = in_sizes[1] / 2;
    const int use_bf16 = (N <= CB_CAP) ? 1 : 0;
    const int nk = N * KCL;
    const int ntiles = (N + TM - 1) / TM;

    cudaFuncSetAttribute(fused_mlp_softmax,
                         cudaFuncAttributeMaxDynamicSharedMemorySize, SMEM_BYTES);

    int grid = 296;                      // 2 CTAs x 148 SMs, persistent
    if (grid > ntiles) grid = ntiles;
    fused_mlp_softmax<<<grid, NT, SMEM_BYTES>>>(x, W1, b1, W2, b2, out,
                                                N, ntiles, use_bf16);

    edge_sum_kernel<<<1184, 256>>>(ei, out, E, N, use_bf16,
                                   out, nk, out_size > nk ? 1 : 0);
}

// round 8
// speedup vs baseline: 4.6422x; 1.0128x over previous
#include <cuda_runtime.h>
#include <cuda_fp16.h>
#include <cuda_bf16.h>
#include <cstdint>

#define D_IN 128
#define D_H  256
#define KCL  16
#define TM   64
#define NT   256

// ---- smem layout (32-bit word offsets) ----
#define SM_XS  0                       // xs  [64][68]  fp16x2 kpairs
#define SM_W1  (64 * 68)               // W1h [256][68] fp16x2 (n-major, kpair cols)
#define SM_W2  (SM_W1 + 256 * 68)      // W2h [16][132] fp16x2
#define SM_B1  (SM_W2 + 16 * 132)      // b1  [256] fp32
#define SM_B2  (SM_B1 + 256)           // b2  [16]  fp32
#define SM_TOT (SM_B2 + 16)            // 24144 words
#define SMEM_BYTES (SM_TOT * 4)        // 96576 B -> 2 CTAs/SM

// overlays of the xs region (4352 words), used after phase 1:
//   stg: 8 warps x [32][17] = 4352 words (two half-K passes)
//   P:   [64][66] = 4224 words
#define STGP 17
#define PP 66

#define CB_CAP 131072
__device__ uint4 g_Cb[CB_CAP * 2];     // bf16 copy of C (32 B/row)
__device__ float g_edge_sum;
__device__ int   g_done;

__device__ __forceinline__ uint32_t pack_h2(float a, float b) {
    __half2 h = __floats2half2_rn(a, b);
    return *(uint32_t*)&h;
}

__device__ __forceinline__ void mma_f16(float* d, const uint32_t* a, const uint32_t* b) {
    asm volatile(
        "mma.sync.aligned.m16n8k16.row.col.f32.f16.f16.f32 "
        "{%0,%1,%2,%3}, {%4,%5,%6,%7}, {%8,%9}, {%0,%1,%2,%3};"
        : "+f"(d[0]), "+f"(d[1]), "+f"(d[2]), "+f"(d[3])
        : "r"(a[0]), "r"(a[1]), "r"(a[2]), "r"(a[3]), "r"(b[0]), "r"(b[1]));
}

// prefetch one tile's x slice (8 x float4 per thread) into registers
__device__ __forceinline__ void load_x_regs(float4* xr, const float4* xv,
                                            int row_base, int N, int r0, int c4)
{
    #pragma unroll
    for (int k = 0; k < 8; k++) {
        int gr = row_base + r0 + 8 * k;
        if (gr < N) xr[k] = __ldg(&xv[(size_t)gr * 32 + c4]);
        else        xr[k] = make_float4(0.f, 0.f, 0.f, 0.f);
    }
}

// Persistent fused MLP+softmax with software-pipelined x prefetch.
__global__ __launch_bounds__(NT, 2)
void fused_mlp_softmax(const float* __restrict__ x,
                       const float* __restrict__ W1,
                       const float* __restrict__ b1,
                       const float* __restrict__ W2,
                       const float* __restrict__ b2,
                       float* __restrict__ C,
                       int N, int ntiles, int write_bf16)
{
    extern __shared__ float smf[];
    uint32_t* smw = (uint32_t*)smf;
    uint32_t* xs  = smw + SM_XS;
    uint32_t* W1s = smw + SM_W1;
    uint32_t* W2s = smw + SM_W2;
    float* b1s = smf + SM_B1;
    float* b2s = smf + SM_B2;

    const int tid = threadIdx.x;
    const int wid = tid >> 5, lane = tid & 31;
    const int g = lane >> 2, tg = lane & 3;
    const int rw = wid >> 2, cw = wid & 3;
    const int rb = rw * 32, nb = cw * 64;

    const int xr0 = tid >> 5;          // this thread's base row (stride 8)
    const int xc4 = tid & 31;          // this thread's float4 column

    // ---- once: pack W1/W2 fp32 -> fp16x2 smem ----
    for (int i = tid; i < 256 * 64; i += NT) {
        int n = i & 255, kp = i >> 8;
        W1s[n * 68 + kp] = pack_h2(W1[(2 * kp) * D_H + n], W1[(2 * kp + 1) * D_H + n]);
    }
    for (int i = tid; i < 16 * 128; i += NT) {
        int kk = i & 15, kp = i >> 4;
        W2s[kk * 132 + kp] = pack_h2(W2[(2 * kp) * KCL + kk], W2[(2 * kp + 1) * KCL + kk]);
    }
    b1s[tid] = b1[tid];
    if (tid < KCL) b2s[tid] = b2[tid];

    const float4* xv = (const float4*)x;
    float4 xr[8];
    int tile = blockIdx.x;
    if (tile < ntiles)
        load_x_regs(xr, xv, tile * TM, N, xr0, xc4);

    for (; tile < ntiles; tile += gridDim.x) {
        const int row_base = tile * TM;

        // ---- phase 0: registers -> fp16x2 smem ----
        #pragma unroll
        for (int k = 0; k < 8; k++) {
            int r = xr0 + 8 * k;
            uint2 u;
            u.x = pack_h2(xr[k].x, xr[k].y);
            u.y = pack_h2(xr[k].z, xr[k].w);
            *(uint2*)&xs[r * 68 + 2 * xc4] = u;
        }
        __syncthreads();

        // ---- phase 1: layer 1 fp16 mma, warp tile 32x64 ----
        float acc[2][8][4];
        #pragma unroll
        for (int mf = 0; mf < 2; mf++)
            #pragma unroll
            for (int nf = 0; nf < 8; nf++)
                #pragma unroll
                for (int q = 0; q < 4; q++) acc[mf][nf][q] = 0.f;

        #pragma unroll 1
        for (int ks = 0; ks < 8; ks++) {
            const int kp0 = 8 * ks + tg;
            uint32_t a[2][4];
            #pragma unroll
            for (int mf = 0; mf < 2; mf++) {
                int r0 = rb + mf * 16 + g;
                a[mf][0] = xs[r0 * 68 + kp0];
                a[mf][1] = xs[(r0 + 8) * 68 + kp0];
                a[mf][2] = xs[r0 * 68 + kp0 + 4];
                a[mf][3] = xs[(r0 + 8) * 68 + kp0 + 4];
            }
            uint32_t b[8][2];
            #pragma unroll
            for (int nf = 0; nf < 8; nf++) {
                int n = nb + nf * 8 + g;
                b[nf][0] = W1s[n * 68 + kp0];
                b[nf][1] = W1s[n * 68 + kp0 + 4];
            }
            #pragma unroll
            for (int mf = 0; mf < 2; mf++)
                #pragma unroll
                for (int nf = 0; nf < 8; nf++)
                    mma_f16(acc[mf][nf], a[mf], b[nf]);
        }
        __syncthreads();   // xs dead; reuse as stg

        // ---- phase 2+3 fused, two half-K passes through xs region ----
        float s2[2][2][4];
        #pragma unroll
        for (int mf = 0; mf < 2; mf++)
            #pragma unroll
            for (int nf2 = 0; nf2 < 2; nf2++)
                #pragma unroll
                for (int q = 0; q < 4; q++) s2[mf][nf2][q] = 0.f;

        uint32_t* stg = xs + wid * 544;

        // ----- pass 0: stage h cols [nb, nb+32) -----
        #pragma unroll
        for (int mf = 0; mf < 2; mf++) {
            #pragma unroll
            for (int nf = 0; nf < 4; nf++) {
                int col = nb + nf * 8 + 2 * tg;
                float bc0 = b1s[col], bc1 = b1s[col + 1];
                int row = mf * 16 + g;
                int kp = (4 * nf + tg) & 15;
                stg[row * STGP + kp] = pack_h2(fmaxf(acc[mf][nf][0] + bc0, 0.f),
                                               fmaxf(acc[mf][nf][1] + bc1, 0.f));
                stg[(row + 8) * STGP + kp] = pack_h2(fmaxf(acc[mf][nf][2] + bc0, 0.f),
                                                     fmaxf(acc[mf][nf][3] + bc1, 0.f));
            }
        }
        __syncwarp();
        {
            const int kbase = (nb >> 1);
            #pragma unroll
            for (int ks = 0; ks < 2; ks++) {
                const int kp0 = 8 * ks + tg;
                uint32_t bb[2][2];
                #pragma unroll
                for (int nf2 = 0; nf2 < 2; nf2++) {
                    int n = nf2 * 8 + g;
                    bb[nf2][0] = W2s[n * 132 + kbase + kp0];
                    bb[nf2][1] = W2s[n * 132 + kbase + kp0 + 4];
                }
                #pragma unroll
                for (int mf = 0; mf < 2; mf++) {
                    int r0 = mf * 16 + g;
                    uint32_t a[4];
                    a[0] = stg[r0 * STGP + kp0];
                    a[1] = stg[(r0 + 8) * STGP + kp0];
                    a[2] = stg[r0 * STGP + kp0 + 4];
                    a[3] = stg[(r0 + 8) * STGP + kp0 + 4];
                    #pragma unroll
                    for (int nf2 = 0; nf2 < 2; nf2++)
                        mma_f16(s2[mf][nf2], a, bb[nf2]);
                }
            }
        }
        __syncwarp();

        // ----- pass 1: stage h cols [nb+32, nb+64) -----
        #pragma unroll
        for (int mf = 0; mf < 2; mf++) {
            #pragma unroll
            for (int nf = 4; nf < 8; nf++) {
                int col = nb + nf * 8 + 2 * tg;
                float bc0 = b1s[col], bc1 = b1s[col + 1];
                int row = mf * 16 + g;
                int kp = (4 * nf + tg) & 15;
                stg[row * STGP + kp] = pack_h2(fmaxf(acc[mf][nf][0] + bc0, 0.f),
                                               fmaxf(acc[mf][nf][1] + bc1, 0.f));
                stg[(row + 8) * STGP + kp] = pack_h2(fmaxf(acc[mf][nf][2] + bc0, 0.f),
                                                     fmaxf(acc[mf][nf][3] + bc1, 0.f));
            }
        }
        __syncwarp();

        // acc is dead now: prefetch next tile's x into registers.
        // LDG latency (~600-1000 cyc) hides under the remaining phases.
        {
            int nt2 = tile + gridDim.x;
            if (nt2 < ntiles)
                load_x_regs(xr, xv, nt2 * TM, N, xr0, xc4);
        }

        {
            const int kbase = (nb >> 1) + 16;
            #pragma unroll
            for (int ks = 0; ks < 2; ks++) {
                const int kp0 = 8 * ks + tg;
                uint32_t bb[2][2];
                #pragma unroll
                for (int nf2 = 0; nf2 < 2; nf2++) {
                    int n = nf2 * 8 + g;
                    bb[nf2][0] = W2s[n * 132 + kbase + kp0];
                    bb[nf2][1] = W2s[n * 132 + kbase + kp0 + 4];
                }
                #pragma unroll
                for (int mf = 0; mf < 2; mf++) {
                    int r0 = mf * 16 + g;
                    uint32_t a[4];
                    a[0] = stg[r0 * STGP + kp0];
                    a[1] = stg[(r0 + 8) * STGP + kp0];
                    a[2] = stg[r0 * STGP + kp0 + 4];
                    a[3] = stg[(r0 + 8) * STGP + kp0 + 4];
                    #pragma unroll
                    for (int nf2 = 0; nf2 < 2; nf2++)
                        mma_f16(s2[mf][nf2], a, bb[nf2]);
                }
            }
        }
        __syncthreads();   // stg dead; reuse xs region as P

        // ---- phase 4: K-partials P[row][cw*16 + kk] ----
        float* P = (float*)xs;
        #pragma unroll
        for (int mf = 0; mf < 2; mf++) {
            #pragma unroll
            for (int nf2 = 0; nf2 < 2; nf2++) {
                int row = rb + mf * 16 + g;
                int kk0 = nf2 * 8 + 2 * tg;
                *(float2*)&P[row * PP + cw * 16 + kk0] =
                    make_float2(s2[mf][nf2][0], s2[mf][nf2][1]);
                *(float2*)&P[(row + 8) * PP + cw * 16 + kk0] =
                    make_float2(s2[mf][nf2][2], s2[mf][nf2][3]);
            }
        }
        __syncthreads();

        // ---- phase 5: reduce, softmax (4-lane segments), coalesced stores ----
        {
            const int row = tid >> 2;
            const int q   = tid & 3;
            const int kb  = 4 * q;

            float sv[4];
            #pragma unroll
            for (int j = 0; j < 4; j++) sv[j] = b2s[kb + j];
            #pragma unroll
            for (int c = 0; c < 4; c++) {
                float2 pA = *(float2*)&P[row * PP + 16 * c + kb];
                float2 pB = *(float2*)&P[row * PP + 16 * c + kb + 2];
                sv[0] += pA.x; sv[1] += pA.y; sv[2] += pB.x; sv[3] += pB.y;
            }
            float m = fmaxf(fmaxf(sv[0], sv[1]), fmaxf(sv[2], sv[3]));
            m = fmaxf(m, __shfl_xor_sync(0xFFFFFFFFu, m, 1, 4));
            m = fmaxf(m, __shfl_xor_sync(0xFFFFFFFFu, m, 2, 4));
            float ssum = 0.f;
            #pragma unroll
            for (int j = 0; j < 4; j++) { sv[j] = __expf(sv[j] - m); ssum += sv[j]; }
            ssum += __shfl_xor_sync(0xFFFFFFFFu, ssum, 1, 4);
            ssum += __shfl_xor_sync(0xFFFFFFFFu, ssum, 2, 4);
            float inv = 1.f / ssum;
            #pragma unroll
            for (int j = 0; j < 4; j++) sv[j] *= inv;

            int gr = row_base + row;
            if (gr < N) {
                *(float4*)&C[(size_t)gr * KCL + kb] =
                    make_float4(sv[0], sv[1], sv[2], sv[3]);
                if (write_bf16) {
                    __nv_bfloat162 h0 = __floats2bfloat162_rn(sv[0], sv[1]);
                    __nv_bfloat162 h1 = __floats2bfloat162_rn(sv[2], sv[3]);
                    uint2 u;
                    u.x = *(uint32_t*)&h0;
                    u.y = *(uint32_t*)&h1;
                    ((uint2*)g_Cb)[(size_t)gr * 4 + q] = u;
                }
            }
        }
        __syncthreads();   // P dead before next tile's xs stores
    }
}

__inline__ __device__ float warp_reduce_sum(float v) {
    #pragma unroll
    for (int o = 16; o > 0; o >>= 1)
        v += __shfl_xor_sync(0xFFFFFFFFu, v, o);
    return v;
}

__device__ __forceinline__ float bf16x8_dot(uint4 a, uint4 b) {
    float2 fa, fb;
    float s = 0.f;
    fa = __bfloat1622float2(*(__nv_bfloat162*)&a.x);
    fb = __bfloat1622float2(*(__nv_bfloat162*)&b.x);
    s += fa.x * fb.x + fa.y * fb.y;
    fa = __bfloat1622float2(*(__nv_bfloat162*)&a.y);
    fb = __bfloat1622float2(*(__nv_bfloat162*)&b.y);
    s += fa.x * fb.x + fa.y * fb.y;
    fa = __bfloat1622float2(*(__nv_bfloat162*)&a.z);
    fb = __bfloat1622float2(*(__nv_bfloat162*)&b.z);
    s += fa.x * fb.x + fa.y * fb.y;
    fa = __bfloat1622float2(*(__nv_bfloat162*)&a.w);
    fb = __bfloat1622float2(*(__nv_bfloat162*)&b.w);
    s += fa.x * fb.x + fa.y * fb.y;
    return s;
}

__global__ __launch_bounds__(256)
void edge_sum_kernel(const void* __restrict__ ei_raw,
                     const float* __restrict__ C,
                     int E, int N, int use_bf16,
                     float* __restrict__ out, int nk, int do_write)
{
    const int tid = threadIdx.x;
    const int* ei32 = (const int*)ei_raw;
    int any = 0;
    #pragma unroll
    for (int s = 0; s < 2; s++) {
        long long j = ((long long)(tid * 2 + s) * E) >> 9;
        any |= ei32[2 * j + 1];
    }
    const int is64 = (__syncthreads_or(any) == 0);

    const int tid_g = blockIdx.x * blockDim.x + tid;
    const int total = gridDim.x * blockDim.x;
    float part = 0.f;

    if (use_bf16) {
        const uint4* Cb = (const uint4*)g_Cb;
        const int half = tid_g & 1;
        const int p0 = tid_g >> 1;
        const int np = total >> 1;
        if (is64) {
            const long long* ei = (const long long*)ei_raw;
            for (int e = p0; e < E; e += np) {
                int u = (int)ei[e];
                int v = (int)ei[(size_t)E + e];
                u = ((unsigned)u < (unsigned)N) ? u : 0;
                v = ((unsigned)v < (unsigned)N) ? v : 0;
                uint4 a = __ldg(&Cb[(size_t)u * 2 + half]);
                uint4 b = __ldg(&Cb[(size_t)v * 2 + half]);
                part += bf16x8_dot(a, b);
            }
        } else {
            for (int e = p0; e < E; e += np) {
                int u = ei32[e];
                int v = ei32[(size_t)E + e];
                u = ((unsigned)u < (unsigned)N) ? u : 0;
                v = ((unsigned)v < (unsigned)N) ? v : 0;
                uint4 a = __ldg(&Cb[(size_t)u * 2 + half]);
                uint4 b = __ldg(&Cb[(size_t)v * 2 + half]);
                part += bf16x8_dot(a, b);
            }
        }
    } else {
        const int lane4 = tid_g & 3;
        const int q0 = tid_g >> 2;
        const int nq = total >> 2;
        const float4* C4 = (const float4*)C;
        if (is64) {
            const long long* ei = (const long long*)ei_raw;
            for (int e = q0; e < E; e += nq) {
                int u = (int)ei[e];
                int v = (int)ei[(size_t)E + e];
                u = ((unsigned)u < (unsigned)N) ? u : 0;
                v = ((unsigned)v < (unsigned)N) ? v : 0;
                float4 a = __ldg(&C4[(size_t)u * 4 + lane4]);
                float4 b = __ldg(&C4[(size_t)v * 4 + lane4]);
                part += a.x * b.x + a.y * b.y + a.z * b.z + a.w * b.w;
            }
        } else {
            for (int e = q0; e < E; e += nq) {
                int u = ei32[e];
                int v = ei32[(size_t)E + e];
                u = ((unsigned)u < (unsigned)N) ? u : 0;
                v = ((unsigned)v < (unsigned)N) ? v : 0;
                float4 a = __ldg(&C4[(size_t)u * 4 + lane4]);
                float4 b = __ldg(&C4[(size_t)v * 4 + lane4]);
                part += a.x * b.x + a.y * b.y + a.z * b.z + a.w * b.w;
            }
        }
    }

    part = warp_reduce_sum(part);
    __shared__ float ws[8];
    int lane = tid & 31, wrp = tid >> 5;
    if (lane == 0) ws[wrp] = part;
    __syncthreads();
    if (tid == 0) {
        float v = 0.f;
        #pragma unroll
        for (int w = 0; w < 8; w++) v += ws[w];
        atomicAdd(&g_edge_sum, v);
        __threadfence();
        int t = atomicAdd(&g_done, 1);
        if (t == gridDim.x - 1) {
            if (do_write) out[nk] = -g_edge_sum / (float)E;
            g_edge_sum = 0.f;
            g_done = 0;
        }
    }
}

extern "C" void kernel_launch(void* const* d_in, const int* in_sizes, int n_in,
                              void* d_out, int out_size)
{
    const float* x  = (const float*)d_in[0];
    const void*  ei = d_in[1];
    const float* W1 = (const float*)d_in[2];
    const float* b1 = (const float*)d_in[3];
    const float* W2 = (const float*)d_in[4];
    const float* b2 = (const float*)d_in[5];
    float* out = (float*)d_out;

    const int N = in_sizes[0] / D_IN;
    const int E = in_sizes[1] / 2;
    const int use_bf16 = (N <= CB_CAP) ? 1 : 0;
    const int nk = N * KCL;
    const int ntiles = (N + TM - 1) / TM;

    cudaFuncSetAttribute(fused_mlp_softmax,
                         cudaFuncAttributeMaxDynamicSharedMemorySize, SMEM_BYTES);

    int grid = 296;                      // 2 CTAs x 148 SMs, persistent
    if (grid > ntiles) grid = ntiles;
    fused_mlp_softmax<<<grid, NT, SMEM_BYTES>>>(x, W1, b1, W2, b2, out,
                                                N, ntiles, use_bf16);

    edge_sum_kernel<<<1184, 256>>>(ei, out, E, N, use_bf16,
                                   out, nk, out_size > nk ? 1 : 0);
}

// round 12
// speedup vs baseline: 4.9031x; 1.0562x over previous
#include <cuda_runtime.h>
#include <cuda_fp16.h>
#include <cstdint>

#define D_IN 128
#define D_H  256
#define KCL  16
#define TM   64
#define NT   256

// ---- smem layout (32-bit word offsets) ----
#define SM_XS  0                       // xs  [64][68]  fp16x2 kpairs
#define SM_W1  (64 * 68)               // W1h [256][68] fp16x2 (n-major, kpair cols)
#define SM_W2  (SM_W1 + 256 * 68)      // W2h [16][132] fp16x2
#define SM_B1  (SM_W2 + 16 * 132)      // b1  [256] fp32
#define SM_B2  (SM_B1 + 256)           // b2  [16]  fp32
#define SM_TOT (SM_B2 + 16)            // 24144 words
#define SMEM_BYTES (SM_TOT * 4)        // 96576 B -> 2 CTAs/SM

// overlays of the xs region (4352 words), used after phase 1
#define STGP 17
#define PP 66

#define CB_CAP 131072
__device__ uint4 g_Cu8[CB_CAP];        // u8 fixed-point copy of C, 16 B/row
__device__ float g_edge_sum;
__device__ int   g_done;

__device__ __forceinline__ uint32_t pack_h2(float a, float b) {
    __half2 h = __floats2half2_rn(a, b);
    return *(uint32_t*)&h;
}

__device__ __forceinline__ void mma_f16(float* d, const uint32_t* a, const uint32_t* b) {
    asm volatile(
        "mma.sync.aligned.m16n8k16.row.col.f32.f16.f16.f32 "
        "{%0,%1,%2,%3}, {%4,%5,%6,%7}, {%8,%9}, {%0,%1,%2,%3};"
        : "+f"(d[0]), "+f"(d[1]), "+f"(d[2]), "+f"(d[3])
        : "r"(a[0]), "r"(a[1]), "r"(a[2]), "r"(a[3]), "r"(b[0]), "r"(b[1]));
}

__device__ __forceinline__ void load_x_regs(float4* xr, const float4* xv,
                                            int row_base, int N, int r0, int c4)
{
    #pragma unroll
    for (int k = 0; k < 8; k++) {
        int gr = row_base + r0 + 8 * k;
        if (gr < N) xr[k] = __ldg(&xv[(size_t)gr * 32 + c4]);
        else        xr[k] = make_float4(0.f, 0.f, 0.f, 0.f);
    }
}

// Persistent fused MLP+softmax with software-pipelined x prefetch (R8 proven).
__global__ __launch_bounds__(NT, 2)
void fused_mlp_softmax(const float* __restrict__ x,
                       const float* __restrict__ W1,
                       const float* __restrict__ b1,
                       const float* __restrict__ W2,
                       const float* __restrict__ b2,
                       float* __restrict__ C,
                       int N, int ntiles, int write_u8)
{
    extern __shared__ float smf[];
    uint32_t* smw = (uint32_t*)smf;
    uint32_t* xs  = smw + SM_XS;
    uint32_t* W1s = smw + SM_W1;
    uint32_t* W2s = smw + SM_W2;
    float* b1s = smf + SM_B1;
    float* b2s = smf + SM_B2;

    const int tid = threadIdx.x;
    const int wid = tid >> 5, lane = tid & 31;
    const int g = lane >> 2, tg = lane & 3;
    const int rw = wid >> 2, cw = wid & 3;
    const int rb = rw * 32, nb = cw * 64;

    const int xr0 = tid >> 5;
    const int xc4 = tid & 31;

    for (int i = tid; i < 256 * 64; i += NT) {
        int n = i & 255, kp = i >> 8;
        W1s[n * 68 + kp] = pack_h2(W1[(2 * kp) * D_H + n], W1[(2 * kp + 1) * D_H + n]);
    }
    for (int i = tid; i < 16 * 128; i += NT) {
        int kk = i & 15, kp = i >> 4;
        W2s[kk * 132 + kp] = pack_h2(W2[(2 * kp) * KCL + kk], W2[(2 * kp + 1) * KCL + kk]);
    }
    b1s[tid] = b1[tid];
    if (tid < KCL) b2s[tid] = b2[tid];

    const float4* xv = (const float4*)x;
    float4 xr[8];
    int tile = blockIdx.x;
    if (tile < ntiles)
        load_x_regs(xr, xv, tile * TM, N, xr0, xc4);

    for (; tile < ntiles; tile += gridDim.x) {
        const int row_base = tile * TM;

        // ---- phase 0: registers -> fp16x2 smem ----
        #pragma unroll
        for (int k = 0; k < 8; k++) {
            int r = xr0 + 8 * k;
            uint2 u;
            u.x = pack_h2(xr[k].x, xr[k].y);
            u.y = pack_h2(xr[k].z, xr[k].w);
            *(uint2*)&xs[r * 68 + 2 * xc4] = u;
        }
        __syncthreads();

        // ---- phase 1: layer 1 fp16 mma, warp tile 32x64 ----
        float acc[2][8][4];
        #pragma unroll
        for (int mf = 0; mf < 2; mf++)
            #pragma unroll
            for (int nf = 0; nf < 8; nf++)
                #pragma unroll
                for (int q = 0; q < 4; q++) acc[mf][nf][q] = 0.f;

        #pragma unroll 1
        for (int ks = 0; ks < 8; ks++) {
            const int kp0 = 8 * ks + tg;
            uint32_t a[2][4];
            #pragma unroll
            for (int mf = 0; mf < 2; mf++) {
                int r0 = rb + mf * 16 + g;
                a[mf][0] = xs[r0 * 68 + kp0];
                a[mf][1] = xs[(r0 + 8) * 68 + kp0];
                a[mf][2] = xs[r0 * 68 + kp0 + 4];
                a[mf][3] = xs[(r0 + 8) * 68 + kp0 + 4];
            }
            uint32_t b[8][2];
            #pragma unroll
            for (int nf = 0; nf < 8; nf++) {
                int n = nb + nf * 8 + g;
                b[nf][0] = W1s[n * 68 + kp0];
                b[nf][1] = W1s[n * 68 + kp0 + 4];
            }
            #pragma unroll
            for (int mf = 0; mf < 2; mf++)
                #pragma unroll
                for (int nf = 0; nf < 8; nf++)
                    mma_f16(acc[mf][nf], a[mf], b[nf]);
        }
        __syncthreads();   // xs dead; reuse as stg

        // ---- phase 2+3 fused, two half-K passes through xs region ----
        float s2[2][2][4];
        #pragma unroll
        for (int mf = 0; mf < 2; mf++)
            #pragma unroll
            for (int nf2 = 0; nf2 < 2; nf2++)
                #pragma unroll
                for (int q = 0; q < 4; q++) s2[mf][nf2][q] = 0.f;

        uint32_t* stg = xs + wid * 544;

        // pass 0
        #pragma unroll
        for (int mf = 0; mf < 2; mf++) {
            #pragma unroll
            for (int nf = 0; nf < 4; nf++) {
                int col = nb + nf * 8 + 2 * tg;
                float bc0 = b1s[col], bc1 = b1s[col + 1];
                int row = mf * 16 + g;
                int kp = (4 * nf + tg) & 15;
                stg[row * STGP + kp] = pack_h2(fmaxf(acc[mf][nf][0] + bc0, 0.f),
                                               fmaxf(acc[mf][nf][1] + bc1, 0.f));
                stg[(row + 8) * STGP + kp] = pack_h2(fmaxf(acc[mf][nf][2] + bc0, 0.f),
                                                     fmaxf(acc[mf][nf][3] + bc1, 0.f));
            }
        }
        __syncwarp();
        {
            const int kbase = (nb >> 1);
            #pragma unroll
            for (int ks = 0; ks < 2; ks++) {
                const int kp0 = 8 * ks + tg;
                uint32_t bb[2][2];
                #pragma unroll
                for (int nf2 = 0; nf2 < 2; nf2++) {
                    int n = nf2 * 8 + g;
                    bb[nf2][0] = W2s[n * 132 + kbase + kp0];
                    bb[nf2][1] = W2s[n * 132 + kbase + kp0 + 4];
                }
                #pragma unroll
                for (int mf = 0; mf < 2; mf++) {
                    int r0 = mf * 16 + g;
                    uint32_t a[4];
                    a[0] = stg[r0 * STGP + kp0];
                    a[1] = stg[(r0 + 8) * STGP + kp0];
                    a[2] = stg[r0 * STGP + kp0 + 4];
                    a[3] = stg[(r0 + 8) * STGP + kp0 + 4];
                    #pragma unroll
                    for (int nf2 = 0; nf2 < 2; nf2++)
                        mma_f16(s2[mf][nf2], a, bb[nf2]);
                }
            }
        }
        __syncwarp();

        // pass 1
        #pragma unroll
        for (int mf = 0; mf < 2; mf++) {
            #pragma unroll
            for (int nf = 4; nf < 8; nf++) {
                int col = nb + nf * 8 + 2 * tg;
                float bc0 = b1s[col], bc1 = b1s[col + 1];
                int row = mf * 16 + g;
                int kp = (4 * nf + tg) & 15;
                stg[row * STGP + kp] = pack_h2(fmaxf(acc[mf][nf][0] + bc0, 0.f),
                                               fmaxf(acc[mf][nf][1] + bc1, 0.f));
                stg[(row + 8) * STGP + kp] = pack_h2(fmaxf(acc[mf][nf][2] + bc0, 0.f),
                                                     fmaxf(acc[mf][nf][3] + bc1, 0.f));
            }
        }
        __syncwarp();

        // acc dead: prefetch next tile's x (latency hides under phases 3b-5)
        {
            int nt2 = tile + gridDim.x;
            if (nt2 < ntiles)
                load_x_regs(xr, xv, nt2 * TM, N, xr0, xc4);
        }

        {
            const int kbase = (nb >> 1) + 16;
            #pragma unroll
            for (int ks = 0; ks < 2; ks++) {
                const int kp0 = 8 * ks + tg;
                uint32_t bb[2][2];
                #pragma unroll
                for (int nf2 = 0; nf2 < 2; nf2++) {
                    int n = nf2 * 8 + g;
                    bb[nf2][0] = W2s[n * 132 + kbase + kp0];
                    bb[nf2][1] = W2s[n * 132 + kbase + kp0 + 4];
                }
                #pragma unroll
                for (int mf = 0; mf < 2; mf++) {
                    int r0 = mf * 16 + g;
                    uint32_t a[4];
                    a[0] = stg[r0 * STGP + kp0];
                    a[1] = stg[(r0 + 8) * STGP + kp0];
                    a[2] = stg[r0 * STGP + kp0 + 4];
                    a[3] = stg[(r0 + 8) * STGP + kp0 + 4];
                    #pragma unroll
                    for (int nf2 = 0; nf2 < 2; nf2++)
                        mma_f16(s2[mf][nf2], a, bb[nf2]);
                }
            }
        }
        __syncthreads();   // stg dead; reuse xs region as P

        // ---- phase 4: K-partials ----
        float* P = (float*)xs;
        #pragma unroll
        for (int mf = 0; mf < 2; mf++) {
            #pragma unroll
            for (int nf2 = 0; nf2 < 2; nf2++) {
                int row = rb + mf * 16 + g;
                int kk0 = nf2 * 8 + 2 * tg;
                *(float2*)&P[row * PP + cw * 16 + kk0] =
                    make_float2(s2[mf][nf2][0], s2[mf][nf2][1]);
                *(float2*)&P[(row + 8) * PP + cw * 16 + kk0] =
                    make_float2(s2[mf][nf2][2], s2[mf][nf2][3]);
            }
        }
        __syncthreads();

        // ---- phase 5: reduce, softmax, stores (fp32 C + u8 fixed-point copy) ----
        {
            const int row = tid >> 2;
            const int q   = tid & 3;
            const int kb  = 4 * q;

            float sv[4];
            #pragma unroll
            for (int j = 0; j < 4; j++) sv[j] = b2s[kb + j];
            #pragma unroll
            for (int c = 0; c < 4; c++) {
                float2 pA = *(float2*)&P[row * PP + 16 * c + kb];
                float2 pB = *(float2*)&P[row * PP + 16 * c + kb + 2];
                sv[0] += pA.x; sv[1] += pA.y; sv[2] += pB.x; sv[3] += pB.y;
            }
            float m = fmaxf(fmaxf(sv[0], sv[1]), fmaxf(sv[2], sv[3]));
            m = fmaxf(m, __shfl_xor_sync(0xFFFFFFFFu, m, 1, 4));
            m = fmaxf(m, __shfl_xor_sync(0xFFFFFFFFu, m, 2, 4));
            float ssum = 0.f;
            #pragma unroll
            for (int j = 0; j < 4; j++) { sv[j] = __expf(sv[j] - m); ssum += sv[j]; }
            ssum += __shfl_xor_sync(0xFFFFFFFFu, ssum, 1, 4);
            ssum += __shfl_xor_sync(0xFFFFFFFFu, ssum, 2, 4);
            float inv = 1.f / ssum;
            #pragma unroll
            for (int j = 0; j < 4; j++) sv[j] *= inv;

            int gr = row_base + row;
            if (gr < N) {
                *(float4*)&C[(size_t)gr * KCL + kb] =
                    make_float4(sv[0], sv[1], sv[2], sv[3]);
                if (write_u8) {
                    uint32_t v0 = __float2uint_rn(sv[0] * 255.f);
                    uint32_t v1 = __float2uint_rn(sv[1] * 255.f);
                    uint32_t v2 = __float2uint_rn(sv[2] * 255.f);
                    uint32_t v3 = __float2uint_rn(sv[3] * 255.f);
                    ((uint32_t*)g_Cu8)[(size_t)gr * 4 + q] =
                        v0 | (v1 << 8) | (v2 << 16) | (v3 << 24);
                }
            }
        }
        __syncthreads();
    }
}

__inline__ __device__ float warp_reduce_sum(float v) {
    #pragma unroll
    for (int o = 16; o > 0; o >>= 1)
        v += __shfl_xor_sync(0xFFFFFFFFu, v, o);
    return v;
}

// exact integer dot of two 16-element u8 rows via dp4a (unsigned overload)
__device__ __forceinline__ unsigned int u8x16_dot(uint4 a, uint4 b) {
    unsigned int s = 0u;
    s = __dp4a(a.x, b.x, s);
    s = __dp4a(a.y, b.y, s);
    s = __dp4a(a.z, b.z, s);
    s = __dp4a(a.w, b.w, s);
    return s;
}

// edge gather + reduce + (last block) finalize; dtype probe integrated
__global__ __launch_bounds__(256)
void edge_sum_kernel(const void* __restrict__ ei_raw,
                     const float* __restrict__ C,
                     int E, int N, int use_u8,
                     float* __restrict__ out, int nk, int do_write,
                     float inv_scale)
{
    const int tid = threadIdx.x;
    const int* ei32 = (const int*)ei_raw;
    int any = 0;
    #pragma unroll
    for (int s = 0; s < 2; s++) {
        long long j = ((long long)(tid * 2 + s) * E) >> 9;
        any |= ei32[2 * j + 1];
    }
    const int is64 = (__syncthreads_or(any) == 0);

    const int tid_g = blockIdx.x * blockDim.x + tid;
    const int total = gridDim.x * blockDim.x;
    float part = 0.f;

    if (use_u8) {
        const uint4* Cu = (const uint4*)g_Cu8;
        if (is64) {
            const long long* ei = (const long long*)ei_raw;
            for (int e = tid_g; e < E; e += total) {
                int u = (int)ei[e];
                int v = (int)ei[(size_t)E + e];
                u = ((unsigned)u < (unsigned)N) ? u : 0;
                v = ((unsigned)v < (unsigned)N) ? v : 0;
                uint4 a = __ldg(&Cu[u]);
                uint4 b = __ldg(&Cu[v]);
                part += (float)u8x16_dot(a, b);
            }
        } else {
            for (int e = tid_g; e < E; e += total) {
                int u = ei32[e];
                int v = ei32[(size_t)E + e];
                u = ((unsigned)u < (unsigned)N) ? u : 0;
                v = ((unsigned)v < (unsigned)N) ? v : 0;
                uint4 a = __ldg(&Cu[u]);
                uint4 b = __ldg(&Cu[v]);
                part += (float)u8x16_dot(a, b);
            }
        }
    } else {
        // fp32 fallback: 4 lanes per edge
        const int lane4 = tid_g & 3;
        const int q0 = tid_g >> 2;
        const int nq = total >> 2;
        const float4* C4 = (const float4*)C;
        if (is64) {
            const long long* ei = (const long long*)ei_raw;
            for (int e = q0; e < E; e += nq) {
                int u = (int)ei[e];
                int v = (int)ei[(size_t)E + e];
                u = ((unsigned)u < (unsigned)N) ? u : 0;
                v = ((unsigned)v < (unsigned)N) ? v : 0;
                float4 a = __ldg(&C4[(size_t)u * 4 + lane4]);
                float4 b = __ldg(&C4[(size_t)v * 4 + lane4]);
                part += a.x * b.x + a.y * b.y + a.z * b.z + a.w * b.w;
            }
        } else {
            for (int e = q0; e < E; e += nq) {
                int u = ei32[e];
                int v = ei32[(size_t)E + e];
                u = ((unsigned)u < (unsigned)N) ? u : 0;
                v = ((unsigned)v < (unsigned)N) ? v : 0;
                float4 a = __ldg(&C4[(size_t)u * 4 + lane4]);
                float4 b = __ldg(&C4[(size_t)v * 4 + lane4]);
                part += a.x * b.x + a.y * b.y + a.z * b.z + a.w * b.w;
            }
        }
    }

    part = warp_reduce_sum(part);
    __shared__ float ws[8];
    int lane = tid & 31, wrp = tid >> 5;
    if (lane == 0) ws[wrp] = part;
    __syncthreads();
    if (tid == 0) {
        float v = 0.f;
        #pragma unroll
        for (int w = 0; w < 8; w++) v += ws[w];
        atomicAdd(&g_edge_sum, v);
        __threadfence();
        int t = atomicAdd(&g_done, 1);
        if (t == gridDim.x - 1) {
            if (do_write) out[nk] = -g_edge_sum * inv_scale / (float)E;
            g_edge_sum = 0.f;
            g_done = 0;
        }
    }
}

extern "C" void kernel_launch(void* const* d_in, const int* in_sizes, int n_in,
                              void* d_out, int out_size)
{
    const float* x  = (const float*)d_in[0];
    const void*  ei = d_in[1];
    const float* W1 = (const float*)d_in[2];
    const float* b1 = (const float*)d_in[3];
    const float* W2 = (const float*)d_in[4];
    const float* b2 = (const float*)d_in[5];
    float* out = (float*)d_out;

    const int N = in_sizes[0] / D_IN;
    const int E = in_sizes[1] / 2;
    const int use_u8 = (N <= CB_CAP) ? 1 : 0;
    const int nk = N * KCL;
    const int ntiles = (N + TM - 1) / TM;
    const float inv_scale = use_u8 ? (1.0f / (255.0f * 255.0f)) : 1.0f;

    cudaFuncSetAttribute(fused_mlp_softmax,
                         cudaFuncAttributeMaxDynamicSharedMemorySize, SMEM_BYTES);

    int grid = 296;                      // 2 CTAs x 148 SMs, persistent
    if (grid > ntiles) grid = ntiles;
    fused_mlp_softmax<<<grid, NT, SMEM_BYTES>>>(x, W1, b1, W2, b2, out,
                                                N, ntiles, use_u8);

    edge_sum_kernel<<<1184, 256>>>(ei, out, E, N, use_u8,
                                   out, nk, out_size > nk ? 1 : 0, inv_scale);
}

// round 13
// speedup vs baseline: 4.9055x; 1.0005x over previous
#include <cuda_runtime.h>
#include <cuda_fp16.h>
#include <cstdint>

#define D_IN 128
#define D_H  256
#define KCL  16
#define TM   64
#define NT   256

// ---- smem layout (32-bit word offsets) ----
#define SM_XS  0                       // xs  [64][68]  fp16x2 kpairs
#define SM_W1  (64 * 68)               // W1h [256][68] fp16x2 (n-major, kpair cols)
#define SM_W2  (SM_W1 + 256 * 68)      // W2h [16][132] fp16x2
#define SM_B1  (SM_W2 + 16 * 132)      // b1  [256] fp32
#define SM_B2  (SM_B1 + 256)           // b2  [16]  fp32
#define SM_TOT (SM_B2 + 16)            // 24144 words
#define SMEM_BYTES (SM_TOT * 4)        // 96576 B -> 2 CTAs/SM

// overlays of the xs region (4352 words), used after phase 1
#define STGP 17
#define PP 66

#define CB_CAP 131072
__device__ uint4 g_Cu8[CB_CAP];        // u8 fixed-point copy of C, 16 B/row
__device__ float g_edge_sum;
__device__ int   g_done;

__device__ __forceinline__ uint32_t pack_h2(float a, float b) {
    __half2 h = __floats2half2_rn(a, b);
    return *(uint32_t*)&h;
}

__device__ __forceinline__ void mma_f16(float* d, const uint32_t* a, const uint32_t* b) {
    asm volatile(
        "mma.sync.aligned.m16n8k16.row.col.f32.f16.f16.f32 "
        "{%0,%1,%2,%3}, {%4,%5,%6,%7}, {%8,%9}, {%0,%1,%2,%3};"
        : "+f"(d[0]), "+f"(d[1]), "+f"(d[2]), "+f"(d[3])
        : "r"(a[0]), "r"(a[1]), "r"(a[2]), "r"(a[3]), "r"(b[0]), "r"(b[1]));
}

__device__ __forceinline__ void load_x_regs(float4* xr, const float4* xv,
                                            int row_base, int N, int r0, int c4)
{
    #pragma unroll
    for (int k = 0; k < 8; k++) {
        int gr = row_base + r0 + 8 * k;
        if (gr < N) xr[k] = __ldg(&xv[(size_t)gr * 32 + c4]);
        else        xr[k] = make_float4(0.f, 0.f, 0.f, 0.f);
    }
}

// Persistent fused MLP+softmax, x prefetch + pipelined phase-1 B-fragments.
__global__ __launch_bounds__(NT, 2)
void fused_mlp_softmax(const float* __restrict__ x,
                       const float* __restrict__ W1,
                       const float* __restrict__ b1,
                       const float* __restrict__ W2,
                       const float* __restrict__ b2,
                       float* __restrict__ C,
                       int N, int ntiles, int write_u8)
{
    extern __shared__ float smf[];
    uint32_t* smw = (uint32_t*)smf;
    uint32_t* xs  = smw + SM_XS;
    uint32_t* W1s = smw + SM_W1;
    uint32_t* W2s = smw + SM_W2;
    float* b1s = smf + SM_B1;
    float* b2s = smf + SM_B2;

    const int tid = threadIdx.x;
    const int wid = tid >> 5, lane = tid & 31;
    const int g = lane >> 2, tg = lane & 3;
    const int rw = wid >> 2, cw = wid & 3;
    const int rb = rw * 32, nb = cw * 64;

    const int xr0 = tid >> 5;
    const int xc4 = tid & 31;

    for (int i = tid; i < 256 * 64; i += NT) {
        int n = i & 255, kp = i >> 8;
        W1s[n * 68 + kp] = pack_h2(W1[(2 * kp) * D_H + n], W1[(2 * kp + 1) * D_H + n]);
    }
    for (int i = tid; i < 16 * 128; i += NT) {
        int kk = i & 15, kp = i >> 4;
        W2s[kk * 132 + kp] = pack_h2(W2[(2 * kp) * KCL + kk], W2[(2 * kp + 1) * KCL + kk]);
    }
    b1s[tid] = b1[tid];
    if (tid < KCL) b2s[tid] = b2[tid];

    const float4* xv = (const float4*)x;
    float4 xr[8];
    int tile = blockIdx.x;
    if (tile < ntiles)
        load_x_regs(xr, xv, tile * TM, N, xr0, xc4);

    for (; tile < ntiles; tile += gridDim.x) {
        const int row_base = tile * TM;

        // ---- phase 0: registers -> fp16x2 smem ----
        #pragma unroll
        for (int k = 0; k < 8; k++) {
            int r = xr0 + 8 * k;
            uint2 u;
            u.x = pack_h2(xr[k].x, xr[k].y);
            u.y = pack_h2(xr[k].z, xr[k].w);
            *(uint2*)&xs[r * 68 + 2 * xc4] = u;
        }
        __syncthreads();

        // ---- phase 1: layer 1 fp16 mma, warp tile 32x64, B double-buffered ----
        float acc[2][8][4];
        #pragma unroll
        for (int mf = 0; mf < 2; mf++)
            #pragma unroll
            for (int nf = 0; nf < 8; nf++)
                #pragma unroll
                for (int q = 0; q < 4; q++) acc[mf][nf][q] = 0.f;

        uint32_t bfr[2][8][2];
        {
            const int kp0 = tg;
            #pragma unroll
            for (int nf = 0; nf < 8; nf++) {
                int n = nb + nf * 8 + g;
                bfr[0][nf][0] = W1s[n * 68 + kp0];
                bfr[0][nf][1] = W1s[n * 68 + kp0 + 4];
            }
        }
        #pragma unroll
        for (int ks = 0; ks < 8; ks++) {
            const int cur = ks & 1, nxt = cur ^ 1;
            const int kp0 = 8 * ks + tg;
            uint32_t a[2][4];
            #pragma unroll
            for (int mf = 0; mf < 2; mf++) {
                int r0 = rb + mf * 16 + g;
                a[mf][0] = xs[r0 * 68 + kp0];
                a[mf][1] = xs[(r0 + 8) * 68 + kp0];
                a[mf][2] = xs[r0 * 68 + kp0 + 4];
                a[mf][3] = xs[(r0 + 8) * 68 + kp0 + 4];
            }
            if (ks < 7) {
                const int kp1 = kp0 + 8;
                #pragma unroll
                for (int nf = 0; nf < 8; nf++) {
                    int n = nb + nf * 8 + g;
                    bfr[nxt][nf][0] = W1s[n * 68 + kp1];
                    bfr[nxt][nf][1] = W1s[n * 68 + kp1 + 4];
                }
            }
            #pragma unroll
            for (int mf = 0; mf < 2; mf++)
                #pragma unroll
                for (int nf = 0; nf < 8; nf++)
                    mma_f16(acc[mf][nf], a[mf], bfr[cur][nf]);
        }
        __syncthreads();   // xs dead; reuse as stg

        // ---- phase 2+3 fused, two half-K passes through xs region ----
        float s2[2][2][4];
        #pragma unroll
        for (int mf = 0; mf < 2; mf++)
            #pragma unroll
            for (int nf2 = 0; nf2 < 2; nf2++)
                #pragma unroll
                for (int q = 0; q < 4; q++) s2[mf][nf2][q] = 0.f;

        uint32_t* stg = xs + wid * 544;

        // pass 0
        #pragma unroll
        for (int mf = 0; mf < 2; mf++) {
            #pragma unroll
            for (int nf = 0; nf < 4; nf++) {
                int col = nb + nf * 8 + 2 * tg;
                float bc0 = b1s[col], bc1 = b1s[col + 1];
                int row = mf * 16 + g;
                int kp = (4 * nf + tg) & 15;
                stg[row * STGP + kp] = pack_h2(fmaxf(acc[mf][nf][0] + bc0, 0.f),
                                               fmaxf(acc[mf][nf][1] + bc1, 0.f));
                stg[(row + 8) * STGP + kp] = pack_h2(fmaxf(acc[mf][nf][2] + bc0, 0.f),
                                                     fmaxf(acc[mf][nf][3] + bc1, 0.f));
            }
        }
        __syncwarp();
        {
            const int kbase = (nb >> 1);
            #pragma unroll
            for (int ks = 0; ks < 2; ks++) {
                const int kp0 = 8 * ks + tg;
                uint32_t bb[2][2];
                #pragma unroll
                for (int nf2 = 0; nf2 < 2; nf2++) {
                    int n = nf2 * 8 + g;
                    bb[nf2][0] = W2s[n * 132 + kbase + kp0];
                    bb[nf2][1] = W2s[n * 132 + kbase + kp0 + 4];
                }
                #pragma unroll
                for (int mf = 0; mf < 2; mf++) {
                    int r0 = mf * 16 + g;
                    uint32_t a[4];
                    a[0] = stg[r0 * STGP + kp0];
                    a[1] = stg[(r0 + 8) * STGP + kp0];
                    a[2] = stg[r0 * STGP + kp0 + 4];
                    a[3] = stg[(r0 + 8) * STGP + kp0 + 4];
                    #pragma unroll
                    for (int nf2 = 0; nf2 < 2; nf2++)
                        mma_f16(s2[mf][nf2], a, bb[nf2]);
                }
            }
        }
        __syncwarp();

        // pass 1
        #pragma unroll
        for (int mf = 0; mf < 2; mf++) {
            #pragma unroll
            for (int nf = 4; nf < 8; nf++) {
                int col = nb + nf * 8 + 2 * tg;
                float bc0 = b1s[col], bc1 = b1s[col + 1];
                int row = mf * 16 + g;
                int kp = (4 * nf + tg) & 15;
                stg[row * STGP + kp] = pack_h2(fmaxf(acc[mf][nf][0] + bc0, 0.f),
                                               fmaxf(acc[mf][nf][1] + bc1, 0.f));
                stg[(row + 8) * STGP + kp] = pack_h2(fmaxf(acc[mf][nf][2] + bc0, 0.f),
                                                     fmaxf(acc[mf][nf][3] + bc1, 0.f));
            }
        }
        __syncwarp();

        // acc dead: prefetch next tile's x
        {
            int nt2 = tile + gridDim.x;
            if (nt2 < ntiles)
                load_x_regs(xr, xv, nt2 * TM, N, xr0, xc4);
        }

        {
            const int kbase = (nb >> 1) + 16;
            #pragma unroll
            for (int ks = 0; ks < 2; ks++) {
                const int kp0 = 8 * ks + tg;
                uint32_t bb[2][2];
                #pragma unroll
                for (int nf2 = 0; nf2 < 2; nf2++) {
                    int n = nf2 * 8 + g;
                    bb[nf2][0] = W2s[n * 132 + kbase + kp0];
                    bb[nf2][1] = W2s[n * 132 + kbase + kp0 + 4];
                }
                #pragma unroll
                for (int mf = 0; mf < 2; mf++) {
                    int r0 = mf * 16 + g;
                    uint32_t a[4];
                    a[0] = stg[r0 * STGP + kp0];
                    a[1] = stg[(r0 + 8) * STGP + kp0];
                    a[2] = stg[r0 * STGP + kp0 + 4];
                    a[3] = stg[(r0 + 8) * STGP + kp0 + 4];
                    #pragma unroll
                    for (int nf2 = 0; nf2 < 2; nf2++)
                        mma_f16(s2[mf][nf2], a, bb[nf2]);
                }
            }
        }
        __syncthreads();   // stg dead; reuse xs region as P

        // ---- phase 4: K-partials ----
        float* P = (float*)xs;
        #pragma unroll
        for (int mf = 0; mf < 2; mf++) {
            #pragma unroll
            for (int nf2 = 0; nf2 < 2; nf2++) {
                int row = rb + mf * 16 + g;
                int kk0 = nf2 * 8 + 2 * tg;
                *(float2*)&P[row * PP + cw * 16 + kk0] =
                    make_float2(s2[mf][nf2][0], s2[mf][nf2][1]);
                *(float2*)&P[(row + 8) * PP + cw * 16 + kk0] =
                    make_float2(s2[mf][nf2][2], s2[mf][nf2][3]);
            }
        }
        __syncthreads();

        // ---- phase 5: reduce, softmax, stores (fp32 C + u8 copy) ----
        {
            const int row = tid >> 2;
            const int q   = tid & 3;
            const int kb  = 4 * q;

            float sv[4];
            #pragma unroll
            for (int j = 0; j < 4; j++) sv[j] = b2s[kb + j];
            #pragma unroll
            for (int c = 0; c < 4; c++) {
                float2 pA = *(float2*)&P[row * PP + 16 * c + kb];
                float2 pB = *(float2*)&P[row * PP + 16 * c + kb + 2];
                sv[0] += pA.x; sv[1] += pA.y; sv[2] += pB.x; sv[3] += pB.y;
            }
            float m = fmaxf(fmaxf(sv[0], sv[1]), fmaxf(sv[2], sv[3]));
            m = fmaxf(m, __shfl_xor_sync(0xFFFFFFFFu, m, 1, 4));
            m = fmaxf(m, __shfl_xor_sync(0xFFFFFFFFu, m, 2, 4));
            float ssum = 0.f;
            #pragma unroll
            for (int j = 0; j < 4; j++) { sv[j] = __expf(sv[j] - m); ssum += sv[j]; }
            ssum += __shfl_xor_sync(0xFFFFFFFFu, ssum, 1, 4);
            ssum += __shfl_xor_sync(0xFFFFFFFFu, ssum, 2, 4);
            float inv = 1.f / ssum;
            #pragma unroll
            for (int j = 0; j < 4; j++) sv[j] *= inv;

            int gr = row_base + row;
            if (gr < N) {
                *(float4*)&C[(size_t)gr * KCL + kb] =
                    make_float4(sv[0], sv[1], sv[2], sv[3]);
                if (write_u8) {
                    uint32_t v0 = __float2uint_rn(sv[0] * 255.f);
                    uint32_t v1 = __float2uint_rn(sv[1] * 255.f);
                    uint32_t v2 = __float2uint_rn(sv[2] * 255.f);
                    uint32_t v3 = __float2uint_rn(sv[3] * 255.f);
                    ((uint32_t*)g_Cu8)[(size_t)gr * 4 + q] =
                        v0 | (v1 << 8) | (v2 << 16) | (v3 << 24);
                }
            }
        }
        __syncthreads();
    }
}

__inline__ __device__ float warp_reduce_sum(float v) {
    #pragma unroll
    for (int o = 16; o > 0; o >>= 1)
        v += __shfl_xor_sync(0xFFFFFFFFu, v, o);
    return v;
}

__device__ __forceinline__ unsigned int u8x16_dot(uint4 a, uint4 b) {
    unsigned int s = 0u;
    s = __dp4a(a.x, b.x, s);
    s = __dp4a(a.y, b.y, s);
    s = __dp4a(a.z, b.z, s);
    s = __dp4a(a.w, b.w, s);
    return s;
}

// edge gather + reduce + (last block) finalize; 2 edges/thread/iter
__global__ __launch_bounds__(256)
void edge_sum_kernel(const void* __restrict__ ei_raw,
                     const float* __restrict__ C,
                     int E, int N, int use_u8,
                     float* __restrict__ out, int nk, int do_write,
                     float inv_scale)
{
    const int tid = threadIdx.x;
    const int* ei32 = (const int*)ei_raw;
    int any = 0;
    #pragma unroll
    for (int s = 0; s < 2; s++) {
        long long j = ((long long)(tid * 2 + s) * E) >> 9;
        any |= ei32[2 * j + 1];
    }
    const int is64 = (__syncthreads_or(any) == 0);

    const int tid_g = blockIdx.x * blockDim.x + tid;
    const int total = gridDim.x * blockDim.x;
    const int npairs = E >> 1;
    float part = 0.f;

    if (use_u8) {
        const uint4* Cu = (const uint4*)g_Cu8;
        if (is64) {
            const longlong2* eu = (const longlong2*)ei_raw;             // pairs of src
            const longlong2* ev = (const longlong2*)((const long long*)ei_raw + E);
            for (int p = tid_g; p < npairs; p += total) {
                longlong2 uu = __ldg(&eu[p]);
                longlong2 vv = __ldg(&ev[p]);
                int u0 = (int)uu.x, u1 = (int)uu.y;
                int v0 = (int)vv.x, v1 = (int)vv.y;
                u0 = ((unsigned)u0 < (unsigned)N) ? u0 : 0;
                u1 = ((unsigned)u1 < (unsigned)N) ? u1 : 0;
                v0 = ((unsigned)v0 < (unsigned)N) ? v0 : 0;
                v1 = ((unsigned)v1 < (unsigned)N) ? v1 : 0;
                uint4 a0 = __ldg(&Cu[u0]);
                uint4 b0 = __ldg(&Cu[v0]);
                uint4 a1 = __ldg(&Cu[u1]);
                uint4 b1 = __ldg(&Cu[v1]);
                part += (float)(u8x16_dot(a0, b0) + u8x16_dot(a1, b1));
            }
            if (tid_g == 0 && (E & 1)) {
                int u = (int)((const long long*)ei_raw)[E - 1];
                int v = (int)((const long long*)ei_raw)[2 * (size_t)E - 1];
                u = ((unsigned)u < (unsigned)N) ? u : 0;
                v = ((unsigned)v < (unsigned)N) ? v : 0;
                part += (float)u8x16_dot(__ldg(&Cu[u]), __ldg(&Cu[v]));
            }
        } else {
            const int2* eu = (const int2*)ei_raw;
            const int2* ev = (const int2*)(ei32 + E);
            for (int p = tid_g; p < npairs; p += total) {
                int2 uu = __ldg(&eu[p]);
                int2 vv = __ldg(&ev[p]);
                int u0 = uu.x, u1 = uu.y, v0 = vv.x, v1 = vv.y;
                u0 = ((unsigned)u0 < (unsigned)N) ? u0 : 0;
                u1 = ((unsigned)u1 < (unsigned)N) ? u1 : 0;
                v0 = ((unsigned)v0 < (unsigned)N) ? v0 : 0;
                v1 = ((unsigned)v1 < (unsigned)N) ? v1 : 0;
                uint4 a0 = __ldg(&Cu[u0]);
                uint4 b0 = __ldg(&Cu[v0]);
                uint4 a1 = __ldg(&Cu[u1]);
                uint4 b1 = __ldg(&Cu[v1]);
                part += (float)(u8x16_dot(a0, b0) + u8x16_dot(a1, b1));
            }
            if (tid_g == 0 && (E & 1)) {
                int u = ei32[E - 1];
                int v = ei32[2 * (size_t)E - 1];
                u = ((unsigned)u < (unsigned)N) ? u : 0;
                v = ((unsigned)v < (unsigned)N) ? v : 0;
                part += (float)u8x16_dot(__ldg(&Cu[u]), __ldg(&Cu[v]));
            }
        }
    } else {
        // fp32 fallback: 4 lanes per edge
        const int lane4 = tid_g & 3;
        const int q0 = tid_g >> 2;
        const int nq = total >> 2;
        const float4* C4 = (const float4*)C;
        if (is64) {
            const long long* ei = (const long long*)ei_raw;
            for (int e = q0; e < E; e += nq) {
                int u = (int)ei[e];
                int v = (int)ei[(size_t)E + e];
                u = ((unsigned)u < (unsigned)N) ? u : 0;
                v = ((unsigned)v < (unsigned)N) ? v : 0;
                float4 a = __ldg(&C4[(size_t)u * 4 + lane4]);
                float4 b = __ldg(&C4[(size_t)v * 4 + lane4]);
                part += a.x * b.x + a.y * b.y + a.z * b.z + a.w * b.w;
            }
        } else {
            for (int e = q0; e < E; e += nq) {
                int u = ei32[e];
                int v = ei32[(size_t)E + e];
                u = ((unsigned)u < (unsigned)N) ? u : 0;
                v = ((unsigned)v < (unsigned)N) ? v : 0;
                float4 a = __ldg(&C4[(size_t)u * 4 + lane4]);
                float4 b = __ldg(&C4[(size_t)v * 4 + lane4]);
                part += a.x * b.x + a.y * b.y + a.z * b.z + a.w * b.w;
            }
        }
    }

    part = warp_reduce_sum(part);
    __shared__ float ws[8];
    int lane = tid & 31, wrp = tid >> 5;
    if (lane == 0) ws[wrp] = part;
    __syncthreads();
    if (tid == 0) {
        float v = 0.f;
        #pragma unroll
        for (int w = 0; w < 8; w++) v += ws[w];
        atomicAdd(&g_edge_sum, v);
        __threadfence();
        int t = atomicAdd(&g_done, 1);
        if (t == gridDim.x - 1) {
            if (do_write) out[nk] = -g_edge_sum * inv_scale / (float)E;
            g_edge_sum = 0.f;
            g_done = 0;
        }
    }
}

extern "C" void kernel_launch(void* const* d_in, const int* in_sizes, int n_in,
                              void* d_out, int out_size)
{
    const float* x  = (const float*)d_in[0];
    const void*  ei = d_in[1];
    const float* W1 = (const float*)d_in[2];
    const float* b1 = (const float*)d_in[3];
    const float* W2 = (const float*)d_in[4];
    const float* b2 = (const float*)d_in[5];
    float* out = (float*)d_out;

    const int N = in_sizes[0] / D_IN;
    const int E = in_sizes[1] / 2;
    const int use_u8 = (N <= CB_CAP) ? 1 : 0;
    const int nk = N * KCL;
    const int ntiles = (N + TM - 1) / TM;
    const float inv_scale = use_u8 ? (1.0f / (255.0f * 255.0f)) : 1.0f;

    cudaFuncSetAttribute(fused_mlp_softmax,
                         cudaFuncAttributeMaxDynamicSharedMemorySize, SMEM_BYTES);

    int grid = 296;                      // 2 CTAs x 148 SMs, persistent
    if (grid > ntiles) grid = ntiles;
    fused_mlp_softmax<<<grid, NT, SMEM_BYTES>>>(x, W1, b1, W2, b2, out,
                                                N, ntiles, use_u8);

    edge_sum_kernel<<<1184, 256>>>(ei, out, E, N, use_u8,
                                   out, nk, out_size > nk ? 1 : 0, inv_scale);
}